// round 1
// baseline (speedup 1.0000x reference)
#include <cuda_runtime.h>

// Problem constants
#define BB 16
#define CC 128
#define PP 512
#define TT 32
#define HH 2
#define DD 64
#define EE (DD * TT)   // 2048
#define O3 (3 * CC)    // 384

static __device__ __forceinline__ unsigned long long pack2(float x, float y) {
    unsigned long long r;
    asm("mov.b64 %0, {%1, %2};" : "=l"(r) : "f"(x), "f"(y));
    return r;
}
static __device__ __forceinline__ unsigned long long fma2(unsigned long long a,
                                                          unsigned long long b,
                                                          unsigned long long c) {
    unsigned long long d;
    asm("fma.rn.f32x2 %0, %1, %2, %3;" : "=l"(d) : "l"(a), "l"(b), "l"(c));
    return d;
}
static __device__ __forceinline__ float2 unpack2(unsigned long long v) {
    float2 f;
    asm("mov.b64 {%0, %1}, %2;" : "=f"(f.x), "=f"(f.y) : "l"(v));
    return f;
}

// Scratch (device globals: allocation-free per harness rules)
__device__ float g_WT[CC * O3];                          // W transposed: [c][o]
__device__ float g_q[(size_t)BB * HH * PP * EE];         // 134 MB, pre-scaled by D^-0.5
__device__ float g_k[(size_t)BB * HH * PP * EE];         // 134 MB
__device__ float g_v[(size_t)BB * HH * PP * EE];         // 134 MB
__device__ float g_dots[(size_t)BB * HH * PP * PP];      // 33.5 MB

// ---------------------------------------------------------------------------
// K0: transpose W (384x128, o-major) -> WT (128x384, c-major) for coalesced reads
// ---------------------------------------------------------------------------
__global__ void wt_kernel(const float* __restrict__ W) {
    int i = blockIdx.x * blockDim.x + threadIdx.x;
    if (i < CC * O3) {
        int o = i / CC, c = i % CC;
        g_WT[c * O3 + o] = W[i];
    }
}

// ---------------------------------------------------------------------------
// K1: QKV projection. One block per (b,p). QKV_tile(384x32) = W(384x128) @ X(128x32) + b
// Writes Q/K/V into (B,H,P,E) layout with e = d*T + t. Q pre-scaled.
// ---------------------------------------------------------------------------
__global__ void __launch_bounds__(384) qkv_kernel(const float* __restrict__ x,
                                                  const float* __restrict__ bias) {
    __shared__ float Xs[CC * TT];  // [c][t], 16 KB
    int bp = blockIdx.x;
    int b = bp / PP, p = bp % PP;
    int tid = threadIdx.x;

    // Load X tile: element (c,t) at x[((b*CC + c)*PP + p)*TT + t]
    const float4* x4 = (const float4*)(x + ((size_t)b * CC * PP + p) * TT);
    float4* Xs4 = (float4*)Xs;
    for (int i = tid; i < CC * TT / 4; i += 384) {
        int c = i >> 3, t4 = i & 7;
        Xs4[i] = x4[(size_t)c * (PP * TT / 4) + t4];
    }
    __syncthreads();

    int o = tid;  // output channel 0..383
    float bv = bias[o];
    unsigned long long acc[16];
    unsigned long long binit = pack2(bv, bv);
#pragma unroll
    for (int j = 0; j < 16; j++) acc[j] = binit;

    const unsigned long long* Xs2 = (const unsigned long long*)Xs;
#pragma unroll 4
    for (int c = 0; c < CC; c++) {
        float w = __ldg(&g_WT[c * O3 + o]);   // coalesced across threads
        unsigned long long wd = pack2(w, w);
#pragma unroll
        for (int j = 0; j < 16; j++)
            acc[j] = fma2(wd, Xs2[c * 16 + j], acc[j]);
    }

    // Scatter to q/k/v with layout [b][h][p][d*T + t]
    int kind = o / CC;        // 0=q 1=k 2=v
    int oc = o % CC;
    int h = oc / DD, d = oc % DD;
    float* dst = (kind == 0) ? g_q : (kind == 1) ? g_k : g_v;
    float mul = (kind == 0) ? 0.125f : 1.0f;  // D^-0.5 = 1/8
    size_t off = (((size_t)b * HH + h) * PP + p) * EE + (size_t)d * TT;
    float2* dst2 = (float2*)(dst + off);
#pragma unroll
    for (int j = 0; j < 16; j++) {
        float2 v = unpack2(acc[j]);
        v.x *= mul; v.y *= mul;
        dst2[j] = v;
    }
}

// ---------------------------------------------------------------------------
// K2: dots = Qs @ K^T per (b,h). GEMM-NT 512x512x2048.
// Tile M=128, N=64, Ktile=16; 256 threads, 8x4 micro-tile, f32x2 FMAs.
// ---------------------------------------------------------------------------
__global__ void __launch_bounds__(256) dots_kernel() {
    __shared__ float As[16][132];  // [k][m]
    __shared__ float Bs[16][68];   // [k][n]
    int bh = blockIdx.z;
    int m0 = blockIdx.y * 128;
    int n0 = blockIdx.x * 64;
    const float* Qb = g_q + (size_t)bh * PP * EE;
    const float* Kb = g_k + (size_t)bh * PP * EE;
    int tid = threadIdx.x;
    int ty = tid >> 4, tx = tid & 15;

    unsigned long long acc[8][2];
#pragma unroll
    for (int i = 0; i < 8; i++) { acc[i][0] = 0ull; acc[i][1] = 0ull; }

    for (int kk = 0; kk < EE; kk += 16) {
        // A tile: 128 rows x 16 k, transpose-on-store
#pragma unroll
        for (int s = 0; s < 2; s++) {
            int idx = tid + s * 256;
            int r = idx >> 2, k4 = idx & 3;
            float4 v = *(const float4*)(Qb + (size_t)(m0 + r) * EE + kk + k4 * 4);
            As[k4 * 4 + 0][r] = v.x; As[k4 * 4 + 1][r] = v.y;
            As[k4 * 4 + 2][r] = v.z; As[k4 * 4 + 3][r] = v.w;
        }
        // B tile: 64 rows x 16 k, transpose-on-store
        {
            int r = tid >> 2, k4 = tid & 3;
            float4 v = *(const float4*)(Kb + (size_t)(n0 + r) * EE + kk + k4 * 4);
            Bs[k4 * 4 + 0][r] = v.x; Bs[k4 * 4 + 1][r] = v.y;
            Bs[k4 * 4 + 2][r] = v.z; Bs[k4 * 4 + 3][r] = v.w;
        }
        __syncthreads();
#pragma unroll
        for (int k = 0; k < 16; k++) {
            float4 a0 = *(const float4*)&As[k][ty * 8];
            float4 a1 = *(const float4*)&As[k][ty * 8 + 4];
            unsigned long long b0 = *(const unsigned long long*)&Bs[k][tx * 4];
            unsigned long long b1 = *(const unsigned long long*)&Bs[k][tx * 4 + 2];
            float av[8] = {a0.x, a0.y, a0.z, a0.w, a1.x, a1.y, a1.z, a1.w};
#pragma unroll
            for (int mm = 0; mm < 8; mm++) {
                unsigned long long wd = pack2(av[mm], av[mm]);
                acc[mm][0] = fma2(wd, b0, acc[mm][0]);
                acc[mm][1] = fma2(wd, b1, acc[mm][1]);
            }
        }
        __syncthreads();
    }

#pragma unroll
    for (int mm = 0; mm < 8; mm++) {
        float2 v0 = unpack2(acc[mm][0]);
        float2 v1 = unpack2(acc[mm][1]);
        float4 o = make_float4(v0.x, v0.y, v1.x, v1.y);
        *(float4*)(g_dots + ((size_t)bh * PP + m0 + ty * 8 + mm) * PP + n0 + tx * 4) = o;
    }
}

// ---------------------------------------------------------------------------
// K3: row softmax over g_dots (rows of length 512). One block (128 thr) per row.
// ---------------------------------------------------------------------------
__global__ void __launch_bounds__(128) softmax_kernel() {
    size_t row = blockIdx.x;
    float* r = g_dots + row * PP;
    int tid = threadIdx.x;
    float4 v = ((float4*)r)[tid];

    float m = fmaxf(fmaxf(v.x, v.y), fmaxf(v.z, v.w));
#pragma unroll
    for (int o = 16; o; o >>= 1) m = fmaxf(m, __shfl_xor_sync(0xffffffffu, m, o));
    __shared__ float red[4];
    int wid = tid >> 5;
    if ((tid & 31) == 0) red[wid] = m;
    __syncthreads();
    m = fmaxf(fmaxf(red[0], red[1]), fmaxf(red[2], red[3]));

    v.x = expf(v.x - m); v.y = expf(v.y - m);
    v.z = expf(v.z - m); v.w = expf(v.w - m);
    float s = v.x + v.y + v.z + v.w;
#pragma unroll
    for (int o = 16; o; o >>= 1) s += __shfl_xor_sync(0xffffffffu, s, o);
    __syncthreads();
    if ((tid & 31) == 0) red[wid] = s;
    __syncthreads();
    float inv = 1.0f / (red[0] + red[1] + red[2] + red[3]);
    v.x *= inv; v.y *= inv; v.z *= inv; v.w *= inv;
    ((float4*)r)[tid] = v;
}

// ---------------------------------------------------------------------------
// K4: out = attn @ V per (b,h). GEMM-NN 512x2048x512, epilogue scatters to
// (B,C,P,T) output layout. Tile M=128(p), N=64(e), Ktile=16(q).
// ---------------------------------------------------------------------------
__global__ void __launch_bounds__(256) out_kernel(float* __restrict__ out) {
    __shared__ float As[16][132];  // [k][m]  (attn)
    __shared__ float Bs[16][68];   // [k][n]  (V)
    int bh = blockIdx.z;
    int m0 = blockIdx.y * 128;
    int n0 = blockIdx.x * 64;
    const float* Ab = g_dots + (size_t)bh * PP * PP;
    const float* Vb = g_v + (size_t)bh * PP * EE;
    int tid = threadIdx.x;
    int ty = tid >> 4, tx = tid & 15;

    unsigned long long acc[8][2];
#pragma unroll
    for (int i = 0; i < 8; i++) { acc[i][0] = 0ull; acc[i][1] = 0ull; }

    for (int kk = 0; kk < PP; kk += 16) {
        // attn tile: 128 rows x 16 k, transpose-on-store
#pragma unroll
        for (int s = 0; s < 2; s++) {
            int idx = tid + s * 256;
            int r = idx >> 2, k4 = idx & 3;
            float4 v = *(const float4*)(Ab + (size_t)(m0 + r) * PP + kk + k4 * 4);
            As[k4 * 4 + 0][r] = v.x; As[k4 * 4 + 1][r] = v.y;
            As[k4 * 4 + 2][r] = v.z; As[k4 * 4 + 3][r] = v.w;
        }
        // V tile: 16 rows x 64 n, natural layout (coalesced)
        {
            int k = tid >> 4, c4 = tid & 15;
            float4 v = *(const float4*)(Vb + (size_t)(kk + k) * EE + n0 + c4 * 4);
            *(float4*)&Bs[k][c4 * 4] = v;
        }
        __syncthreads();
#pragma unroll
        for (int k = 0; k < 16; k++) {
            float4 a0 = *(const float4*)&As[k][ty * 8];
            float4 a1 = *(const float4*)&As[k][ty * 8 + 4];
            unsigned long long b0 = *(const unsigned long long*)&Bs[k][tx * 4];
            unsigned long long b1 = *(const unsigned long long*)&Bs[k][tx * 4 + 2];
            float av[8] = {a0.x, a0.y, a0.z, a0.w, a1.x, a1.y, a1.z, a1.w};
#pragma unroll
            for (int mm = 0; mm < 8; mm++) {
                unsigned long long wd = pack2(av[mm], av[mm]);
                acc[mm][0] = fma2(wd, b0, acc[mm][0]);
                acc[mm][1] = fma2(wd, b1, acc[mm][1]);
            }
        }
        __syncthreads();
    }

    // Epilogue: out[b, h*D + d, p, t] with e = n0 + tx*4 = d*32 + t
    int b = bh >> 1, h = bh & 1;
    int e = n0 + tx * 4;
    int d = e >> 5, t = e & 31;
#pragma unroll
    for (int mm = 0; mm < 8; mm++) {
        int p = m0 + ty * 8 + mm;
        float2 v0 = unpack2(acc[mm][0]);
        float2 v1 = unpack2(acc[mm][1]);
        float4 o = make_float4(v0.x, v0.y, v1.x, v1.y);
        *(float4*)(out + (((size_t)b * CC + h * DD + d) * PP + p) * TT + t) = o;
    }
}

// ---------------------------------------------------------------------------
extern "C" void kernel_launch(void* const* d_in, const int* in_sizes, int n_in,
                              void* d_out, int out_size) {
    const float* x = (const float*)d_in[0];
    const float* W = (const float*)d_in[1];
    const float* b = (const float*)d_in[2];
    float* out = (float*)d_out;

    wt_kernel<<<(CC * O3 + 255) / 256, 256>>>(W);
    qkv_kernel<<<BB * PP, 384>>>(x, b);

    dim3 g2(PP / 64, PP / 128, BB * HH);
    dots_kernel<<<g2, 256>>>();

    softmax_kernel<<<BB * HH * PP, 128>>>();

    dim3 g3(EE / 64, PP / 128, BB * HH);
    out_kernel<<<g3, 256>>>(out);
}

// round 3
// speedup vs baseline: 1.6604x; 1.6604x over previous
#include <cuda_runtime.h>
#include <cuda_bf16.h>
#include <cstdint>

// Problem constants
#define BB 16
#define CC 128
#define PP 512
#define TT 32
#define HH 2
#define DD 64
#define EE (DD * TT)   // 2048
#define O3 (3 * CC)    // 384

// ======================== f32x2 helpers (FFMA2) ========================
static __device__ __forceinline__ unsigned long long pack2(float x, float y) {
    unsigned long long r;
    asm("mov.b64 %0, {%1, %2};" : "=l"(r) : "f"(x), "f"(y));
    return r;
}
static __device__ __forceinline__ unsigned long long fma2(unsigned long long a,
                                                          unsigned long long b,
                                                          unsigned long long c) {
    unsigned long long d;
    asm("fma.rn.f32x2 %0, %1, %2, %3;" : "=l"(d) : "l"(a), "l"(b), "l"(c));
    return d;
}
static __device__ __forceinline__ float2 unpack2(unsigned long long v) {
    float2 f;
    asm("mov.b64 {%0, %1}, %2;" : "=f"(f.x), "=f"(f.y) : "l"(v));
    return f;
}

// ======================== mma.sync helpers (sm_80-class, assembles on sm_103) ==
static __device__ __forceinline__ uint32_t smem_u32(const void* p) {
    uint32_t a;
    asm("{ .reg .u64 t; cvta.to.shared.u64 t, %1; cvt.u32.u64 %0, t; }" : "=r"(a) : "l"(p));
    return a;
}
#define LDSM4(r0, r1, r2, r3, a) \
    asm volatile("ldmatrix.sync.aligned.m8n8.x4.shared.b16 {%0,%1,%2,%3}, [%4];" \
        : "=r"(r0), "=r"(r1), "=r"(r2), "=r"(r3) : "r"(a))
#define MMA16816(d, a, b) \
    asm volatile("mma.sync.aligned.m16n8k16.row.col.f32.bf16.bf16.f32 " \
        "{%0,%1,%2,%3}, {%4,%5,%6,%7}, {%8,%9}, {%0,%1,%2,%3};" \
        : "+f"((d)[0]), "+f"((d)[1]), "+f"((d)[2]), "+f"((d)[3]) \
        : "r"((a)[0]), "r"((a)[1]), "r"((a)[2]), "r"((a)[3]), "r"((b)[0]), "r"((b)[1]))
#define CP_ASYNC16(s, g) \
    asm volatile("cp.async.cg.shared.global [%0], [%1], 16;" :: "r"(s), "l"(g) : "memory")
#define CP_COMMIT() asm volatile("cp.async.commit_group;" ::: "memory")

// ======================== scratch (device globals) ========================
__device__ float g_WT[CC * O3];
__device__ __nv_bfloat16 g_q_hi[(size_t)BB * HH * PP * EE];
__device__ __nv_bfloat16 g_q_lo[(size_t)BB * HH * PP * EE];
__device__ __nv_bfloat16 g_k_hi[(size_t)BB * HH * PP * EE];
__device__ __nv_bfloat16 g_k_lo[(size_t)BB * HH * PP * EE];
__device__ float         g_v[(size_t)BB * HH * PP * EE];
__device__ __nv_bfloat16 g_vt_hi[(size_t)BB * HH * EE * PP];   // [bh][e][p]
__device__ __nv_bfloat16 g_vt_lo[(size_t)BB * HH * EE * PP];
__device__ float         g_dots[(size_t)BB * HH * PP * PP];
__device__ __nv_bfloat16 g_attn_hi[(size_t)BB * HH * PP * PP];
__device__ __nv_bfloat16 g_attn_lo[(size_t)BB * HH * PP * PP];

static __device__ __forceinline__ void split_bf16(float v, __nv_bfloat16& hi, __nv_bfloat16& lo) {
    hi = __float2bfloat16(v);
    lo = __float2bfloat16(v - __bfloat162float(hi));
}

// ---------------------------------------------------------------------------
// K0: transpose W -> WT[c][o]
// ---------------------------------------------------------------------------
__global__ void wt_kernel(const float* __restrict__ W) {
    int i = blockIdx.x * blockDim.x + threadIdx.x;
    if (i < CC * O3) {
        int o = i / CC, c = i % CC;
        g_WT[c * O3 + o] = W[i];
    }
}

// ---------------------------------------------------------------------------
// K1: QKV projection (f32x2). q,k emitted as bf16 hi/lo splits; v as fp32.
// ---------------------------------------------------------------------------
__global__ void __launch_bounds__(384) qkv_kernel(const float* __restrict__ x,
                                                  const float* __restrict__ bias) {
    __shared__ float Xs[CC * TT];
    int bp = blockIdx.x;
    int b = bp / PP, p = bp % PP;
    int tid = threadIdx.x;

    const float4* x4 = (const float4*)(x + ((size_t)b * CC * PP + p) * TT);
    float4* Xs4 = (float4*)Xs;
    for (int i = tid; i < CC * TT / 4; i += 384) {
        int c = i >> 3, t4 = i & 7;
        Xs4[i] = x4[(size_t)c * (PP * TT / 4) + t4];
    }
    __syncthreads();

    int o = tid;
    float bv = bias[o];
    unsigned long long acc[16];
    unsigned long long binit = pack2(bv, bv);
#pragma unroll
    for (int j = 0; j < 16; j++) acc[j] = binit;

    const unsigned long long* Xs2 = (const unsigned long long*)Xs;
#pragma unroll 4
    for (int c = 0; c < CC; c++) {
        float w = __ldg(&g_WT[c * O3 + o]);
        unsigned long long wd = pack2(w, w);
#pragma unroll
        for (int j = 0; j < 16; j++)
            acc[j] = fma2(wd, Xs2[c * 16 + j], acc[j]);
    }

    int kind = o / CC;
    int oc = o % CC;
    int h = oc / DD, d = oc % DD;
    size_t off = (((size_t)b * HH + h) * PP + p) * EE + (size_t)d * TT;

    if (kind == 2) {
        float2* dst2 = (float2*)(g_v + off);
#pragma unroll
        for (int j = 0; j < 16; j++) dst2[j] = unpack2(acc[j]);
    } else {
        float mul = (kind == 0) ? 0.125f : 1.0f;  // fold D^-0.5 into q
        __nv_bfloat16 hi[32], lo[32];
#pragma unroll
        for (int j = 0; j < 16; j++) {
            float2 v = unpack2(acc[j]);
            split_bf16(v.x * mul, hi[2 * j], lo[2 * j]);
            split_bf16(v.y * mul, hi[2 * j + 1], lo[2 * j + 1]);
        }
        __nv_bfloat16* dh = ((kind == 0) ? g_q_hi : g_k_hi) + off;
        __nv_bfloat16* dl = ((kind == 0) ? g_q_lo : g_k_lo) + off;
        const uint4* sh = (const uint4*)hi;
        const uint4* sl = (const uint4*)lo;
#pragma unroll
        for (int j = 0; j < 4; j++) {
            ((uint4*)dh)[j] = sh[j];
            ((uint4*)dl)[j] = sl[j];
        }
    }
}

// ---------------------------------------------------------------------------
// K1b: transpose V fp32 [bh][p][e] -> VT bf16 hi/lo [bh][e][p]
// ---------------------------------------------------------------------------
__global__ void __launch_bounds__(256) vt_kernel() {
    __shared__ float tile[32][33];
    int bh = blockIdx.z;
    int e0 = blockIdx.x * 32;
    int p0 = blockIdx.y * 32;
    int tx = threadIdx.x, ty = threadIdx.y;

    const float* src = g_v + (size_t)bh * PP * EE;
#pragma unroll
    for (int i = 0; i < 4; i++) {
        int p = p0 + ty + i * 8;
        tile[ty + i * 8][tx] = src[(size_t)p * EE + e0 + tx];
    }
    __syncthreads();

    __nv_bfloat16* dh = g_vt_hi + (size_t)bh * EE * PP;
    __nv_bfloat16* dl = g_vt_lo + (size_t)bh * EE * PP;
#pragma unroll
    for (int i = 0; i < 4; i++) {
        int e = e0 + ty + i * 8;
        float v = tile[tx][ty + i * 8];
        __nv_bfloat16 hi, lo;
        split_bf16(v, hi, lo);
        dh[(size_t)e * PP + p0 + tx] = hi;
        dl[(size_t)e * PP + p0 + tx] = lo;
    }
}

// ---------------------------------------------------------------------------
// K2/K4: NT GEMM via mma.sync bf16 3-split, fp32 accum.
// D[M=512, N] = A[M,K] @ B[N,K]^T per bh. Block tile 128x128, Ktile 64.
// 256 threads = 8 warps (2x4), warp tile 64x32 = 4x4 m16n8k16.
// SMEM per stage: Ah|Al|Bh|Bl, each 128 rows x 128B, SW128 swizzle. 2 stages.
// mode 0: write fp32 dots. mode 1: scatter to output (B,C,P,T).
// ---------------------------------------------------------------------------
#define STAGE_BYTES 65536
#define MMA_SMEM_REQ (2 * STAGE_BYTES + 1024)

__global__ void __launch_bounds__(256, 1) mma_nt_kernel(
    const __nv_bfloat16* __restrict__ Ah, const __nv_bfloat16* __restrict__ Al,
    const __nv_bfloat16* __restrict__ Bh, const __nv_bfloat16* __restrict__ Bl,
    int Kdim, size_t aStride, size_t bStride, int mode, float* __restrict__ dst)
{
    extern __shared__ char smem[];
    uint32_t base = (smem_u32(smem) + 1023) & ~1023u;

    int tid = threadIdx.x;
    int wid = tid >> 5, lane = tid & 31;
    int bh = blockIdx.z;
    int m0 = blockIdx.y * 128;
    int n0 = blockIdx.x * 128;

    const __nv_bfloat16* A0h = Ah + (size_t)bh * aStride;
    const __nv_bfloat16* A0l = Al + (size_t)bh * aStride;
    const __nv_bfloat16* B0h = Bh + (size_t)bh * bStride;
    const __nv_bfloat16* B0l = Bl + (size_t)bh * bStride;

    // ---- async tile loader: 4 tiles x 128 rows x 128B into stage (it&1) ----
    auto load_tiles = [&](int it) {
        int kk = it * 64;
        uint32_t db = base + (uint32_t)(it & 1) * STAGE_BYTES;
#pragma unroll
        for (int i = 0; i < 16; i++) {
            const int tile = i >> 2;                 // compile-time under unroll
            int c = tid + i * 256;
            int r = (c >> 3) & 127;
            int j = c & 7;
            const __nv_bfloat16* g =
                (tile == 0 ? A0h : tile == 1 ? A0l : tile == 2 ? B0h : B0l)
                + (size_t)((tile < 2 ? m0 : n0) + r) * Kdim + (kk + j * 8);
            uint32_t s = db + tile * 16384 + r * 128 + ((j * 16) ^ ((r & 7) << 4));
            CP_ASYNC16(s, g);
        }
        CP_COMMIT();
    };

    // warp coordinates
    int warp_m = wid & 1, warp_n = wid >> 1;
    int row_in = lane & 7, mat = lane >> 3;
    uint32_t xorv = (uint32_t)row_in << 4;
    int a_row = warp_m * 64 + (mat & 1) * 8 + row_in;   // + mt*16
    int a_khalf = (mat >> 1) * 16;
    int b_row = warp_n * 32 + (mat >> 1) * 8 + row_in;  // + ntp*16
    int b_khalf = (mat & 1) * 16;

    float acc[4][4][4];
#pragma unroll
    for (int i = 0; i < 4; i++)
#pragma unroll
        for (int j = 0; j < 4; j++)
#pragma unroll
            for (int k = 0; k < 4; k++) acc[i][j][k] = 0.f;

    int iters = Kdim / 64;
    load_tiles(0);

    for (int it = 0; it < iters; it++) {
        if (it + 1 < iters) {
            load_tiles(it + 1);
            asm volatile("cp.async.wait_group 1;" ::: "memory");
        } else {
            asm volatile("cp.async.wait_group 0;" ::: "memory");
        }
        __syncthreads();

        uint32_t db = base + (uint32_t)(it & 1) * STAGE_BYTES;
        uint32_t Ah_b = db, Al_b = db + 16384, Bh_b = db + 32768, Bl_b = db + 49152;

#pragma unroll
        for (int kq = 0; kq < 4; kq++) {
            uint32_t ah[4][4], al[4][4], bhf[4][2], blf[4][2];
            uint32_t a_off = (uint32_t)((kq * 32 + a_khalf) ^ (int)xorv);
            uint32_t b_off = (uint32_t)((kq * 32 + b_khalf) ^ (int)xorv);
#pragma unroll
            for (int mt = 0; mt < 4; mt++) {
                uint32_t ro = (uint32_t)(a_row + mt * 16) * 128;
                LDSM4(ah[mt][0], ah[mt][1], ah[mt][2], ah[mt][3], Ah_b + ro + a_off);
                LDSM4(al[mt][0], al[mt][1], al[mt][2], al[mt][3], Al_b + ro + a_off);
            }
#pragma unroll
            for (int ntp = 0; ntp < 2; ntp++) {
                uint32_t ro = (uint32_t)(b_row + ntp * 16) * 128;
                uint32_t r0, r1, r2, r3;
                LDSM4(r0, r1, r2, r3, Bh_b + ro + b_off);
                bhf[2 * ntp][0] = r0; bhf[2 * ntp][1] = r1;
                bhf[2 * ntp + 1][0] = r2; bhf[2 * ntp + 1][1] = r3;
                LDSM4(r0, r1, r2, r3, Bl_b + ro + b_off);
                blf[2 * ntp][0] = r0; blf[2 * ntp][1] = r1;
                blf[2 * ntp + 1][0] = r2; blf[2 * ntp + 1][1] = r3;
            }
#pragma unroll
            for (int mt = 0; mt < 4; mt++)
#pragma unroll
                for (int nt = 0; nt < 4; nt++) {
                    MMA16816(acc[mt][nt], ah[mt], bhf[nt]);
                    MMA16816(acc[mt][nt], ah[mt], blf[nt]);
                    MMA16816(acc[mt][nt], al[mt], bhf[nt]);
                }
        }
        __syncthreads();   // protect stage before reload at it+2
    }

    // ---- epilogue ----
    int gm = m0 + warp_m * 64 + (lane >> 2);
    if (mode == 0) {
#pragma unroll
        for (int mt = 0; mt < 4; mt++)
#pragma unroll
            for (int nt = 0; nt < 4; nt++) {
                int col = n0 + warp_n * 32 + nt * 8 + (lane & 3) * 2;
                int row = gm + mt * 16;
                float* d0 = dst + ((size_t)bh * PP + row) * PP + col;
                *(float2*)d0 = make_float2(acc[mt][nt][0], acc[mt][nt][1]);
                *(float2*)(d0 + 8 * PP) = make_float2(acc[mt][nt][2], acc[mt][nt][3]);
            }
    } else {
        int b = bh >> 1, h = bh & 1;
#pragma unroll
        for (int mt = 0; mt < 4; mt++)
#pragma unroll
            for (int nt = 0; nt < 4; nt++) {
                int e = n0 + warp_n * 32 + nt * 8 + (lane & 3) * 2;
                int d = e >> 5, t = e & 31;
                int p = gm + mt * 16;
                float* d0 = dst + (((size_t)b * CC + h * DD + d) * PP + p) * TT + t;
                *(float2*)d0 = make_float2(acc[mt][nt][0], acc[mt][nt][1]);
                *(float2*)(d0 + 8 * TT) = make_float2(acc[mt][nt][2], acc[mt][nt][3]);
            }
    }
}

// ---------------------------------------------------------------------------
// K3: row softmax over g_dots; emits attn as bf16 hi/lo splits.
// ---------------------------------------------------------------------------
__global__ void __launch_bounds__(128) softmax_kernel() {
    size_t row = blockIdx.x;
    const float* r = g_dots + row * PP;
    int tid = threadIdx.x;
    float4 v = ((const float4*)r)[tid];

    float m = fmaxf(fmaxf(v.x, v.y), fmaxf(v.z, v.w));
#pragma unroll
    for (int o = 16; o; o >>= 1) m = fmaxf(m, __shfl_xor_sync(0xffffffffu, m, o));
    __shared__ float red[4];
    int wid = tid >> 5;
    if ((tid & 31) == 0) red[wid] = m;
    __syncthreads();
    m = fmaxf(fmaxf(red[0], red[1]), fmaxf(red[2], red[3]));

    v.x = expf(v.x - m); v.y = expf(v.y - m);
    v.z = expf(v.z - m); v.w = expf(v.w - m);
    float s = v.x + v.y + v.z + v.w;
#pragma unroll
    for (int o = 16; o; o >>= 1) s += __shfl_xor_sync(0xffffffffu, s, o);
    __syncthreads();
    if ((tid & 31) == 0) red[wid] = s;
    __syncthreads();
    float inv = 1.0f / (red[0] + red[1] + red[2] + red[3]);
    v.x *= inv; v.y *= inv; v.z *= inv; v.w *= inv;

    __nv_bfloat16 hi[4], lo[4];
    split_bf16(v.x, hi[0], lo[0]); split_bf16(v.y, hi[1], lo[1]);
    split_bf16(v.z, hi[2], lo[2]); split_bf16(v.w, hi[3], lo[3]);
    *(uint2*)(g_attn_hi + row * PP + tid * 4) = *(const uint2*)hi;
    *(uint2*)(g_attn_lo + row * PP + tid * 4) = *(const uint2*)lo;
}

// ---------------------------------------------------------------------------
extern "C" void kernel_launch(void* const* d_in, const int* in_sizes, int n_in,
                              void* d_out, int out_size) {
    const float* x = (const float*)d_in[0];
    const float* W = (const float*)d_in[1];
    const float* b = (const float*)d_in[2];
    float* out = (float*)d_out;

    cudaFuncSetAttribute(mma_nt_kernel, cudaFuncAttributeMaxDynamicSharedMemorySize, MMA_SMEM_REQ);

    wt_kernel<<<(CC * O3 + 255) / 256, 256>>>(W);
    qkv_kernel<<<BB * PP, 384>>>(x, b);

    dim3 gt(EE / 32, PP / 32, BB * HH);
    vt_kernel<<<gt, dim3(32, 8)>>>();

    // dots = Qs @ K^T : M=512, N=512, K=2048
    {
        float* dots = nullptr;
        cudaGetSymbolAddress((void**)&dots, g_dots);
        __nv_bfloat16 *qh, *ql, *kh, *kl;
        cudaGetSymbolAddress((void**)&qh, g_q_hi);
        cudaGetSymbolAddress((void**)&ql, g_q_lo);
        cudaGetSymbolAddress((void**)&kh, g_k_hi);
        cudaGetSymbolAddress((void**)&kl, g_k_lo);
        dim3 g(PP / 128, PP / 128, BB * HH);
        mma_nt_kernel<<<g, 256, MMA_SMEM_REQ>>>(qh, ql, kh, kl, EE,
                                                (size_t)PP * EE, (size_t)PP * EE, 0, dots);
    }

    softmax_kernel<<<BB * HH * PP, 128>>>();

    // out = attn @ V : M=512, N=2048(E), K=512
    {
        __nv_bfloat16 *ah, *al, *vh, *vl;
        cudaGetSymbolAddress((void**)&ah, g_attn_hi);
        cudaGetSymbolAddress((void**)&al, g_attn_lo);
        cudaGetSymbolAddress((void**)&vh, g_vt_hi);
        cudaGetSymbolAddress((void**)&vl, g_vt_lo);
        dim3 g(EE / 128, PP / 128, BB * HH);
        mma_nt_kernel<<<g, 256, MMA_SMEM_REQ>>>(ah, al, vh, vl, PP,
                                                (size_t)PP * PP, (size_t)EE * PP, 1, out);
    }
}

// round 4
// speedup vs baseline: 2.5561x; 1.5395x over previous
#include <cuda_runtime.h>
#include <cuda_bf16.h>
#include <cstdint>

// Problem constants
#define BB 16
#define CC 128
#define PP 512
#define TT 32
#define HH 2
#define DD 64
#define EE (DD * TT)   // 2048
#define O3 (3 * CC)    // 384
#define NN ((size_t)BB * PP * TT)   // 262144 columns of the QKV GEMM

// ======================== mma.sync helpers ========================
static __device__ __forceinline__ uint32_t smem_u32(const void* p) {
    uint32_t a;
    asm("{ .reg .u64 t; cvta.to.shared.u64 t, %1; cvt.u32.u64 %0, t; }" : "=r"(a) : "l"(p));
    return a;
}
#define LDSM4(r0, r1, r2, r3, a) \
    asm volatile("ldmatrix.sync.aligned.m8n8.x4.shared.b16 {%0,%1,%2,%3}, [%4];" \
        : "=r"(r0), "=r"(r1), "=r"(r2), "=r"(r3) : "r"(a))
#define MMA16816(d, a, b) \
    asm volatile("mma.sync.aligned.m16n8k16.row.col.f32.bf16.bf16.f32 " \
        "{%0,%1,%2,%3}, {%4,%5,%6,%7}, {%8,%9}, {%0,%1,%2,%3};" \
        : "+f"((d)[0]), "+f"((d)[1]), "+f"((d)[2]), "+f"((d)[3]) \
        : "r"((a)[0]), "r"((a)[1]), "r"((a)[2]), "r"((a)[3]), "r"((b)[0]), "r"((b)[1]))
#define CP_ASYNC16(s, g) \
    asm volatile("cp.async.cg.shared.global [%0], [%1], 16;" :: "r"(s), "l"(g) : "memory")
#define CP_COMMIT() asm volatile("cp.async.commit_group;" ::: "memory")

// ======================== scratch (device globals) ========================
__device__ __nv_bfloat16 g_w_hi[O3 * CC];
__device__ __nv_bfloat16 g_w_lo[O3 * CC];
__device__ __nv_bfloat16 g_xt_hi[NN * CC];    // [n=(b,p,t)][c]
__device__ __nv_bfloat16 g_xt_lo[NN * CC];
__device__ __nv_bfloat16 g_q_hi[(size_t)BB * HH * PP * EE];
__device__ __nv_bfloat16 g_q_lo[(size_t)BB * HH * PP * EE];
__device__ __nv_bfloat16 g_k_hi[(size_t)BB * HH * PP * EE];
__device__ __nv_bfloat16 g_k_lo[(size_t)BB * HH * PP * EE];
__device__ __nv_bfloat16 g_v_hi[(size_t)BB * HH * PP * EE];
__device__ __nv_bfloat16 g_v_lo[(size_t)BB * HH * PP * EE];
__device__ __nv_bfloat16 g_vt_hi[(size_t)BB * HH * EE * PP];   // [bh][e][p]
__device__ __nv_bfloat16 g_vt_lo[(size_t)BB * HH * EE * PP];
__device__ float         g_dots[(size_t)BB * HH * PP * PP];
__device__ __nv_bfloat16 g_attn_hi[(size_t)BB * HH * PP * PP];
__device__ __nv_bfloat16 g_attn_lo[(size_t)BB * HH * PP * PP];

static __device__ __forceinline__ void split_bf16(float v, __nv_bfloat16& hi, __nv_bfloat16& lo) {
    hi = __float2bfloat16(v);
    lo = __float2bfloat16(v - __bfloat162float(hi));
}

// ---------------------------------------------------------------------------
// K0: split W -> bf16 hi/lo (already K-major: [o][c], c contiguous)
// ---------------------------------------------------------------------------
__global__ void wsplit_kernel(const float* __restrict__ W) {
    int i = blockIdx.x * blockDim.x + threadIdx.x;
    if (i < O3 * CC) split_bf16(W[i], g_w_hi[i], g_w_lo[i]);
}

// ---------------------------------------------------------------------------
// K1: transpose + split x (B,C,P,T) fp32 -> xT bf16 hi/lo [(b,p,t)][c]
// ---------------------------------------------------------------------------
__global__ void __launch_bounds__(256) xsplit_kernel(const float* __restrict__ x) {
    __shared__ float tile[32][33];
    int b = blockIdx.z, p = blockIdx.y, c0 = blockIdx.x * 32;
    int tx = threadIdx.x, ty = threadIdx.y;

    const float* src = x + (((size_t)b * CC + c0) * PP + p) * TT;
#pragma unroll
    for (int i = 0; i < 4; i++) {
        int c = ty + i * 8;
        tile[c][tx] = src[(size_t)c * PP * TT + tx];
    }
    __syncthreads();

    size_t nbase = ((size_t)b * PP + p) * TT;
#pragma unroll
    for (int i = 0; i < 4; i++) {
        int t = ty + i * 8;
        float v = tile[tx][t];
        __nv_bfloat16 hi, lo;
        split_bf16(v, hi, lo);
        size_t off = (nbase + t) * CC + c0 + tx;
        g_xt_hi[off] = hi;
        g_xt_lo[off] = lo;
    }
}

// ---------------------------------------------------------------------------
// K2: transpose V bf16 hi/lo [bh][p][e] -> [bh][e][p]
// ---------------------------------------------------------------------------
__global__ void __launch_bounds__(256) vt_kernel() {
    __shared__ __nv_bfloat16 th[32][34], tl[32][34];
    int bh = blockIdx.z;
    int e0 = blockIdx.x * 32;
    int p0 = blockIdx.y * 32;
    int tx = threadIdx.x, ty = threadIdx.y;

    size_t sbase = (size_t)bh * PP * EE;
#pragma unroll
    for (int i = 0; i < 4; i++) {
        int r = ty + i * 8;
        size_t off = sbase + (size_t)(p0 + r) * EE + e0 + tx;
        th[r][tx] = g_v_hi[off];
        tl[r][tx] = g_v_lo[off];
    }
    __syncthreads();

    size_t dbase = (size_t)bh * EE * PP;
#pragma unroll
    for (int i = 0; i < 4; i++) {
        int e = ty + i * 8;
        size_t off = dbase + (size_t)(e0 + e) * PP + p0 + tx;
        g_vt_hi[off] = th[tx][e];
        g_vt_lo[off] = tl[tx][e];
    }
}

// ---------------------------------------------------------------------------
// Generic NT GEMM via mma.sync bf16 3-split, fp32 accum, 3-stage cp.async.
// D[M,N] = A[M,K] @ B[N,K]^T per blockIdx.z. Block tile 128x128, Ktile 64.
// 256 threads = 8 warps (2x4), warp tile 64x32 = 4x4 m16n8k16.
// mode 0: fp32 dots out. mode 1: scatter to output (B,C,P,T).
// mode 2: QKV epilogue — +bias (dst = bias ptr), q-scale, split-store q/k/v.
// ---------------------------------------------------------------------------
#define STAGE_BYTES 65536
#define NSTAGE 3
#define MMA_SMEM_REQ (NSTAGE * STAGE_BYTES + 1024)

__global__ void __launch_bounds__(256, 1) mma_nt_kernel(
    const __nv_bfloat16* __restrict__ Ah, const __nv_bfloat16* __restrict__ Al,
    const __nv_bfloat16* __restrict__ Bh, const __nv_bfloat16* __restrict__ Bl,
    int Kdim, size_t aStride, size_t bStride, int mode, float* __restrict__ dst)
{
    extern __shared__ char smem[];
    uint32_t base = (smem_u32(smem) + 1023) & ~1023u;

    int tid = threadIdx.x;
    int wid = tid >> 5, lane = tid & 31;
    int bh = blockIdx.z;
    int m0 = blockIdx.y * 128;
    int n0 = blockIdx.x * 128;

    const __nv_bfloat16* A0h = Ah + (size_t)bh * aStride;
    const __nv_bfloat16* A0l = Al + (size_t)bh * aStride;
    const __nv_bfloat16* B0h = Bh + (size_t)bh * bStride;
    const __nv_bfloat16* B0l = Bl + (size_t)bh * bStride;

    // ---- async tile loader: 4 tiles x 128 rows x 128B into stage (it%3) ----
    auto load_tiles = [&](int it) {
        int kk = it * 64;
        uint32_t db = base + (uint32_t)(it % NSTAGE) * STAGE_BYTES;
#pragma unroll
        for (int i = 0; i < 16; i++) {
            const int tile = i >> 2;
            int c = tid + i * 256;
            int r = (c >> 3) & 127;
            int j = c & 7;
            const __nv_bfloat16* g =
                (tile == 0 ? A0h : tile == 1 ? A0l : tile == 2 ? B0h : B0l)
                + (size_t)((tile < 2 ? m0 : n0) + r) * Kdim + (kk + j * 8);
            uint32_t s = db + tile * 16384 + r * 128 + ((j * 16) ^ ((r & 7) << 4));
            CP_ASYNC16(s, g);
        }
        CP_COMMIT();
    };

    // warp coordinates
    int warp_m = wid & 1, warp_n = wid >> 1;
    int row_in = lane & 7, mat = lane >> 3;
    uint32_t xorv = (uint32_t)row_in << 4;
    int a_row = warp_m * 64 + (mat & 1) * 8 + row_in;
    int a_khalf = (mat >> 1) * 16;
    int b_row = warp_n * 32 + (mat >> 1) * 8 + row_in;
    int b_khalf = (mat & 1) * 16;

    float acc[4][4][4];
#pragma unroll
    for (int i = 0; i < 4; i++)
#pragma unroll
        for (int j = 0; j < 4; j++)
#pragma unroll
            for (int k = 0; k < 4; k++) acc[i][j][k] = 0.f;

    int iters = Kdim / 64;
    load_tiles(0);
    if (iters > 1) load_tiles(1);

    for (int it = 0; it < iters; it++) {
        if (it + 1 < iters) {
            asm volatile("cp.async.wait_group 1;" ::: "memory");
        } else {
            asm volatile("cp.async.wait_group 0;" ::: "memory");
        }
        __syncthreads();
        if (it + 2 < iters) load_tiles(it + 2);

        uint32_t db = base + (uint32_t)(it % NSTAGE) * STAGE_BYTES;
        uint32_t Ah_b = db, Al_b = db + 16384, Bh_b = db + 32768, Bl_b = db + 49152;

#pragma unroll
        for (int kq = 0; kq < 4; kq++) {
            uint32_t ah[4][4], al[4][4], bhf[4][2], blf[4][2];
            uint32_t a_off = (uint32_t)((kq * 32 + a_khalf) ^ (int)xorv);
            uint32_t b_off = (uint32_t)((kq * 32 + b_khalf) ^ (int)xorv);
#pragma unroll
            for (int mt = 0; mt < 4; mt++) {
                uint32_t ro = (uint32_t)(a_row + mt * 16) * 128;
                LDSM4(ah[mt][0], ah[mt][1], ah[mt][2], ah[mt][3], Ah_b + ro + a_off);
                LDSM4(al[mt][0], al[mt][1], al[mt][2], al[mt][3], Al_b + ro + a_off);
            }
#pragma unroll
            for (int ntp = 0; ntp < 2; ntp++) {
                uint32_t ro = (uint32_t)(b_row + ntp * 16) * 128;
                uint32_t r0, r1, r2, r3;
                LDSM4(r0, r1, r2, r3, Bh_b + ro + b_off);
                bhf[2 * ntp][0] = r0; bhf[2 * ntp][1] = r1;
                bhf[2 * ntp + 1][0] = r2; bhf[2 * ntp + 1][1] = r3;
                LDSM4(r0, r1, r2, r3, Bl_b + ro + b_off);
                blf[2 * ntp][0] = r0; blf[2 * ntp][1] = r1;
                blf[2 * ntp + 1][0] = r2; blf[2 * ntp + 1][1] = r3;
            }
#pragma unroll
            for (int mt = 0; mt < 4; mt++)
#pragma unroll
                for (int nt = 0; nt < 4; nt++) {
                    MMA16816(acc[mt][nt], ah[mt], bhf[nt]);
                    MMA16816(acc[mt][nt], ah[mt], blf[nt]);
                    MMA16816(acc[mt][nt], al[mt], bhf[nt]);
                }
        }
        __syncthreads();
    }

    // ---- epilogue ----
    if (mode == 0) {
        int gm = m0 + warp_m * 64 + (lane >> 2);
#pragma unroll
        for (int mt = 0; mt < 4; mt++)
#pragma unroll
            for (int nt = 0; nt < 4; nt++) {
                int col = n0 + warp_n * 32 + nt * 8 + (lane & 3) * 2;
                int row = gm + mt * 16;
                float* d0 = dst + ((size_t)bh * PP + row) * PP + col;
                *(float2*)d0 = make_float2(acc[mt][nt][0], acc[mt][nt][1]);
                *(float2*)(d0 + 8 * PP) = make_float2(acc[mt][nt][2], acc[mt][nt][3]);
            }
    } else if (mode == 1) {
        int gm = m0 + warp_m * 64 + (lane >> 2);
        int b = bh >> 1, h = bh & 1;
#pragma unroll
        for (int mt = 0; mt < 4; mt++)
#pragma unroll
            for (int nt = 0; nt < 4; nt++) {
                int e = n0 + warp_n * 32 + nt * 8 + (lane & 3) * 2;
                int d = e >> 5, t = e & 31;
                int p = gm + mt * 16;
                float* d0 = dst + (((size_t)b * CC + h * DD + d) * PP + p) * TT + t;
                *(float2*)d0 = make_float2(acc[mt][nt][0], acc[mt][nt][1]);
                *(float2*)(d0 + 8 * TT) = make_float2(acc[mt][nt][2], acc[mt][nt][3]);
            }
    } else {
        // mode 2: QKV epilogue. dst = bias. kind determined by M tile.
        const float* bias = dst;
        int kind = blockIdx.y;                 // 0=q 1=k 2=v
        __nv_bfloat16* dh = (kind == 0) ? g_q_hi : (kind == 1) ? g_k_hi : g_v_hi;
        __nv_bfloat16* dl = (kind == 0) ? g_q_lo : (kind == 1) ? g_k_lo : g_v_lo;
        float mul = (kind == 0) ? 0.125f : 1.0f;
#pragma unroll
        for (int mt = 0; mt < 4; mt++)
#pragma unroll
            for (int nt = 0; nt < 4; nt++) {
                int n = n0 + warp_n * 32 + nt * 8 + (lane & 3) * 2;
                int b = n >> 14;               // / (P*T)
                int p = (n >> 5) & (PP - 1);
                int t = n & (TT - 1);
#pragma unroll
                for (int half = 0; half < 2; half++) {
                    int o = m0 + warp_m * 64 + mt * 16 + (lane >> 2) + half * 8;
                    float bv = __ldg(&bias[o]);
                    int oc = o & (CC - 1);
                    int h = oc >> 6, d = oc & (DD - 1);
                    float v0 = (acc[mt][nt][2 * half + 0] + bv) * mul;
                    float v1 = (acc[mt][nt][2 * half + 1] + bv) * mul;
                    __nv_bfloat16 h2[2], l2[2];
                    split_bf16(v0, h2[0], l2[0]);
                    split_bf16(v1, h2[1], l2[1]);
                    size_t off = (((size_t)b * HH + h) * PP + p) * EE + d * TT + t;
                    *(uint32_t*)(dh + off) = *(const uint32_t*)h2;
                    *(uint32_t*)(dl + off) = *(const uint32_t*)l2;
                }
            }
    }
}

// ---------------------------------------------------------------------------
// K3: row softmax over g_dots; emits attn as bf16 hi/lo splits.
// ---------------------------------------------------------------------------
__global__ void __launch_bounds__(128) softmax_kernel() {
    size_t row = blockIdx.x;
    const float* r = g_dots + row * PP;
    int tid = threadIdx.x;
    float4 v = ((const float4*)r)[tid];

    float m = fmaxf(fmaxf(v.x, v.y), fmaxf(v.z, v.w));
#pragma unroll
    for (int o = 16; o; o >>= 1) m = fmaxf(m, __shfl_xor_sync(0xffffffffu, m, o));
    __shared__ float red[4];
    int wid = tid >> 5;
    if ((tid & 31) == 0) red[wid] = m;
    __syncthreads();
    m = fmaxf(fmaxf(red[0], red[1]), fmaxf(red[2], red[3]));

    v.x = expf(v.x - m); v.y = expf(v.y - m);
    v.z = expf(v.z - m); v.w = expf(v.w - m);
    float s = v.x + v.y + v.z + v.w;
#pragma unroll
    for (int o = 16; o; o >>= 1) s += __shfl_xor_sync(0xffffffffu, s, o);
    __syncthreads();
    if ((tid & 31) == 0) red[wid] = s;
    __syncthreads();
    float inv = 1.0f / (red[0] + red[1] + red[2] + red[3]);
    v.x *= inv; v.y *= inv; v.z *= inv; v.w *= inv;

    __nv_bfloat16 hi[4], lo[4];
    split_bf16(v.x, hi[0], lo[0]); split_bf16(v.y, hi[1], lo[1]);
    split_bf16(v.z, hi[2], lo[2]); split_bf16(v.w, hi[3], lo[3]);
    *(uint2*)(g_attn_hi + row * PP + tid * 4) = *(const uint2*)hi;
    *(uint2*)(g_attn_lo + row * PP + tid * 4) = *(const uint2*)lo;
}

// ---------------------------------------------------------------------------
extern "C" void kernel_launch(void* const* d_in, const int* in_sizes, int n_in,
                              void* d_out, int out_size) {
    const float* x = (const float*)d_in[0];
    const float* W = (const float*)d_in[1];
    const float* b = (const float*)d_in[2];
    float* out = (float*)d_out;

    cudaFuncSetAttribute(mma_nt_kernel, cudaFuncAttributeMaxDynamicSharedMemorySize, MMA_SMEM_REQ);

    wsplit_kernel<<<(O3 * CC + 255) / 256, 256>>>(W);
    xsplit_kernel<<<dim3(CC / 32, PP, BB), dim3(32, 8)>>>(x);

    // QKV: D[384, 262144] = W @ xT^T, K=128, mode 2
    {
        __nv_bfloat16 *wh, *wl, *xh, *xl;
        cudaGetSymbolAddress((void**)&wh, g_w_hi);
        cudaGetSymbolAddress((void**)&wl, g_w_lo);
        cudaGetSymbolAddress((void**)&xh, g_xt_hi);
        cudaGetSymbolAddress((void**)&xl, g_xt_lo);
        dim3 g((unsigned)(NN / 128), O3 / 128, 1);
        mma_nt_kernel<<<g, 256, MMA_SMEM_REQ>>>(wh, wl, xh, xl, CC,
                                                0, 0, 2, (float*)b);
    }

    dim3 gt(EE / 32, PP / 32, BB * HH);
    vt_kernel<<<gt, dim3(32, 8)>>>();

    // dots = Qs @ K^T : M=512, N=512, K=2048
    {
        float* dots = nullptr;
        cudaGetSymbolAddress((void**)&dots, g_dots);
        __nv_bfloat16 *qh, *ql, *kh, *kl;
        cudaGetSymbolAddress((void**)&qh, g_q_hi);
        cudaGetSymbolAddress((void**)&ql, g_q_lo);
        cudaGetSymbolAddress((void**)&kh, g_k_hi);
        cudaGetSymbolAddress((void**)&kl, g_k_lo);
        dim3 g(PP / 128, PP / 128, BB * HH);
        mma_nt_kernel<<<g, 256, MMA_SMEM_REQ>>>(qh, ql, kh, kl, EE,
                                                (size_t)PP * EE, (size_t)PP * EE, 0, dots);
    }

    softmax_kernel<<<BB * HH * PP, 128>>>();

    // out = attn @ V : M=512, N=2048(E), K=512
    {
        __nv_bfloat16 *ah, *al, *vh, *vl;
        cudaGetSymbolAddress((void**)&ah, g_attn_hi);
        cudaGetSymbolAddress((void**)&al, g_attn_lo);
        cudaGetSymbolAddress((void**)&vh, g_vt_hi);
        cudaGetSymbolAddress((void**)&vl, g_vt_lo);
        dim3 g(EE / 128, PP / 128, BB * HH);
        mma_nt_kernel<<<g, 256, MMA_SMEM_REQ>>>(ah, al, vh, vl, PP,
                                                (size_t)PP * PP, (size_t)EE * PP, 1, out);
    }
}

// round 5
// speedup vs baseline: 2.7991x; 1.0950x over previous
#include <cuda_runtime.h>
#include <cuda_bf16.h>
#include <cstdint>

// Problem constants
#define BB 16
#define CC 128
#define PP 512
#define TT 32
#define HH 2
#define DD 64
#define EE (DD * TT)   // 2048
#define O3 (3 * CC)    // 384
#define NN ((size_t)BB * PP * TT)   // 262144 columns of the QKV GEMM

// ======================== mma.sync helpers ========================
static __device__ __forceinline__ uint32_t smem_u32(const void* p) {
    uint32_t a;
    asm("{ .reg .u64 t; cvta.to.shared.u64 t, %1; cvt.u32.u64 %0, t; }" : "=r"(a) : "l"(p));
    return a;
}
#define LDSM4(r0, r1, r2, r3, a) \
    asm volatile("ldmatrix.sync.aligned.m8n8.x4.shared.b16 {%0,%1,%2,%3}, [%4];" \
        : "=r"(r0), "=r"(r1), "=r"(r2), "=r"(r3) : "r"(a))
#define MMA16816(d, a, b) \
    asm volatile("mma.sync.aligned.m16n8k16.row.col.f32.bf16.bf16.f32 " \
        "{%0,%1,%2,%3}, {%4,%5,%6,%7}, {%8,%9}, {%0,%1,%2,%3};" \
        : "+f"((d)[0]), "+f"((d)[1]), "+f"((d)[2]), "+f"((d)[3]) \
        : "r"((a)[0]), "r"((a)[1]), "r"((a)[2]), "r"((a)[3]), "r"((b)[0]), "r"((b)[1]))
#define CP_ASYNC16(s, g) \
    asm volatile("cp.async.cg.shared.global [%0], [%1], 16;" :: "r"(s), "l"(g) : "memory")
#define CP_COMMIT() asm volatile("cp.async.commit_group;" ::: "memory")

// ======================== scratch (device globals) ========================
__device__ __nv_bfloat16 g_w_hi[O3 * CC];
__device__ __nv_bfloat16 g_w_lo[O3 * CC];
__device__ __nv_bfloat16 g_xt_hi[NN * CC];    // [n=(b,p,t)][c]
__device__ __nv_bfloat16 g_xt_lo[NN * CC];
__device__ __nv_bfloat16 g_q_hi[(size_t)BB * HH * PP * EE];
__device__ __nv_bfloat16 g_q_lo[(size_t)BB * HH * PP * EE];
__device__ __nv_bfloat16 g_k_hi[(size_t)BB * HH * PP * EE];
__device__ __nv_bfloat16 g_k_lo[(size_t)BB * HH * PP * EE];
__device__ __nv_bfloat16 g_v_hi[(size_t)BB * HH * PP * EE];
__device__ __nv_bfloat16 g_v_lo[(size_t)BB * HH * PP * EE];
__device__ __nv_bfloat16 g_vt_hi[(size_t)BB * HH * EE * PP];   // [bh][e][p]
__device__ __nv_bfloat16 g_vt_lo[(size_t)BB * HH * EE * PP];
__device__ float         g_dots[(size_t)BB * HH * PP * PP];
__device__ __nv_bfloat16 g_attn_hi[(size_t)BB * HH * PP * PP];
__device__ __nv_bfloat16 g_attn_lo[(size_t)BB * HH * PP * PP];

static __device__ __forceinline__ void split_bf16(float v, __nv_bfloat16& hi, __nv_bfloat16& lo) {
    hi = __float2bfloat16(v);
    lo = __float2bfloat16(v - __bfloat162float(hi));
}

// ---------------------------------------------------------------------------
// K0: split W -> bf16 hi/lo (already K-major: [o][c], c contiguous)
// ---------------------------------------------------------------------------
__global__ void wsplit_kernel(const float* __restrict__ W) {
    int i = blockIdx.x * blockDim.x + threadIdx.x;
    if (i < O3 * CC) split_bf16(W[i], g_w_hi[i], g_w_lo[i]);
}

// ---------------------------------------------------------------------------
// K1: transpose + split x (B,C,P,T) fp32 -> xT bf16 hi/lo [(b,p,t)][c]
// ---------------------------------------------------------------------------
__global__ void __launch_bounds__(256) xsplit_kernel(const float* __restrict__ x) {
    __shared__ float tile[32][33];
    int b = blockIdx.z, p = blockIdx.y, c0 = blockIdx.x * 32;
    int tx = threadIdx.x, ty = threadIdx.y;

    const float* src = x + (((size_t)b * CC + c0) * PP + p) * TT;
#pragma unroll
    for (int i = 0; i < 4; i++) {
        int c = ty + i * 8;
        tile[c][tx] = src[(size_t)c * PP * TT + tx];
    }
    __syncthreads();

    size_t nbase = ((size_t)b * PP + p) * TT;
#pragma unroll
    for (int i = 0; i < 4; i++) {
        int t = ty + i * 8;
        float v = tile[tx][t];
        __nv_bfloat16 hi, lo;
        split_bf16(v, hi, lo);
        size_t off = (nbase + t) * CC + c0 + tx;
        g_xt_hi[off] = hi;
        g_xt_lo[off] = lo;
    }
}

// ---------------------------------------------------------------------------
// K2: transpose V bf16 hi/lo [bh][p][e] -> [bh][e][p].  64x64 tiles, uint4
// global accesses; hi|lo packed into one uint32 smem word (pitch 65 words).
// ---------------------------------------------------------------------------
__global__ void __launch_bounds__(256) vt_kernel() {
    __shared__ uint32_t tile[64][65];
    int bh = blockIdx.z;
    int e0 = blockIdx.x * 64;
    int p0 = blockIdx.y * 64;
    int tid = threadIdx.x;

    size_t sbase = (size_t)bh * PP * EE;
#pragma unroll
    for (int it = 0; it < 2; it++) {
        int idx = tid + it * 256;
        int p = idx >> 3, ec = idx & 7;
        size_t off = sbase + (size_t)(p0 + p) * EE + e0 + ec * 8;
        uint4 vh = *(const uint4*)(g_v_hi + off);
        uint4 vl = *(const uint4*)(g_v_lo + off);
        const uint16_t* h = (const uint16_t*)&vh;
        const uint16_t* l = (const uint16_t*)&vl;
#pragma unroll
        for (int i = 0; i < 8; i++)
            tile[ec * 8 + i][p] = (uint32_t)h[i] | ((uint32_t)l[i] << 16);
    }
    __syncthreads();

    size_t dbase = (size_t)bh * EE * PP;
#pragma unroll
    for (int it = 0; it < 2; it++) {
        int idx = tid + it * 256;
        int e = idx >> 3, pc = idx & 7;
        uint16_t h[8], l[8];
#pragma unroll
        for (int i = 0; i < 8; i++) {
            uint32_t w = tile[e][pc * 8 + i];
            h[i] = (uint16_t)w;
            l[i] = (uint16_t)(w >> 16);
        }
        size_t off = dbase + (size_t)(e0 + e) * PP + p0 + pc * 8;
        *(uint4*)(g_vt_hi + off) = *(const uint4*)h;
        *(uint4*)(g_vt_lo + off) = *(const uint4*)l;
    }
}

// ---------------------------------------------------------------------------
// Generic NT GEMM via mma.sync bf16 3-split, fp32 accum, 2-stage cp.async.
// D[M,N] = A[M,K] @ B[N,K]^T per blockIdx.z. Block tile 128x256, Ktile 64.
// 256 threads = 8 warps (2x4), warp tile 64x64 = 4x8 m16n8k16, term-major MMA.
// mode 0: fp32 dots out. mode 1: scatter to output (B,C,P,T).
// mode 2: QKV epilogue — +bias (dst = bias ptr), q-scale, split-store q/k/v.
// ---------------------------------------------------------------------------
#define STAGE_BYTES (96 * 1024)
#define MMA_SMEM_REQ (2 * STAGE_BYTES + 1024)

__global__ void __launch_bounds__(256, 1) mma_nt_kernel(
    const __nv_bfloat16* __restrict__ Ah, const __nv_bfloat16* __restrict__ Al,
    const __nv_bfloat16* __restrict__ Bh, const __nv_bfloat16* __restrict__ Bl,
    int Kdim, size_t aStride, size_t bStride, int mode, float* __restrict__ dst)
{
    extern __shared__ char smem[];
    uint32_t base = (smem_u32(smem) + 1023) & ~1023u;

    int tid = threadIdx.x;
    int wid = tid >> 5, lane = tid & 31;
    int bh = blockIdx.z;
    int m0 = blockIdx.y * 128;
    int n0 = blockIdx.x * 256;

    const __nv_bfloat16* A0h = Ah + (size_t)bh * aStride;
    const __nv_bfloat16* A0l = Al + (size_t)bh * aStride;
    const __nv_bfloat16* B0h = Bh + (size_t)bh * bStride;
    const __nv_bfloat16* B0l = Bl + (size_t)bh * bStride;

    // ---- async tile loader: A (2x16KB) + B (2x32KB) into stage (it&1) ----
    auto load_tiles = [&](int it) {
        int kk = it * 64;
        uint32_t db = base + (uint32_t)(it & 1) * STAGE_BYTES;
#pragma unroll
        for (int i = 0; i < 8; i++) {                    // A hi/lo: 128 rows x 128B
            const int tile = i >> 2;
            int c = tid + i * 256;
            int r = (c >> 3) & 127;
            int j = c & 7;
            const __nv_bfloat16* g = (tile ? A0l : A0h)
                + (size_t)(m0 + r) * Kdim + (kk + j * 8);
            uint32_t s = db + tile * 16384 + r * 128 + ((j * 16) ^ ((r & 7) << 4));
            CP_ASYNC16(s, g);
        }
#pragma unroll
        for (int i = 0; i < 16; i++) {                   // B hi/lo: 256 rows x 128B
            const int tile = i >> 3;
            int c = tid + i * 256;
            int r = (c >> 3) & 255;
            int j = c & 7;
            const __nv_bfloat16* g = (tile ? B0l : B0h)
                + (size_t)(n0 + r) * Kdim + (kk + j * 8);
            uint32_t s = db + 32768 + tile * 32768 + r * 128 + ((j * 16) ^ ((r & 7) << 4));
            CP_ASYNC16(s, g);
        }
        CP_COMMIT();
    };

    // warp coordinates: 2 (m) x 4 (n) warps, warp tile 64x64
    int warp_m = wid & 1, warp_n = wid >> 1;
    int row_in = lane & 7, mat = lane >> 3;
    uint32_t xorv = (uint32_t)row_in << 4;
    int a_row = warp_m * 64 + (mat & 1) * 8 + row_in;    // + mt*16
    int a_khalf = (mat >> 1) * 16;
    int b_row = warp_n * 64 + (mat >> 1) * 8 + row_in;   // + ntp*16
    int b_khalf = (mat & 1) * 16;

    float acc[4][8][4];
#pragma unroll
    for (int i = 0; i < 4; i++)
#pragma unroll
        for (int j = 0; j < 8; j++)
#pragma unroll
            for (int k = 0; k < 4; k++) acc[i][j][k] = 0.f;

    int iters = Kdim / 64;
    load_tiles(0);

    for (int it = 0; it < iters; it++) {
        if (it + 1 < iters) {
            load_tiles(it + 1);
            asm volatile("cp.async.wait_group 1;" ::: "memory");
        } else {
            asm volatile("cp.async.wait_group 0;" ::: "memory");
        }
        __syncthreads();

        uint32_t db = base + (uint32_t)(it & 1) * STAGE_BYTES;
        uint32_t Ah_b = db, Al_b = db + 16384, Bh_b = db + 32768, Bl_b = db + 65536;

#pragma unroll
        for (int kq = 0; kq < 4; kq++) {
            uint32_t ah[4][4], al[4][4], bhf[8][2], blf[8][2];
            uint32_t a_off = (uint32_t)((kq * 32 + a_khalf) ^ (int)xorv);
            uint32_t b_off = (uint32_t)((kq * 32 + b_khalf) ^ (int)xorv);
#pragma unroll
            for (int mt = 0; mt < 4; mt++) {
                uint32_t ro = (uint32_t)(a_row + mt * 16) * 128;
                LDSM4(ah[mt][0], ah[mt][1], ah[mt][2], ah[mt][3], Ah_b + ro + a_off);
                LDSM4(al[mt][0], al[mt][1], al[mt][2], al[mt][3], Al_b + ro + a_off);
            }
#pragma unroll
            for (int ntp = 0; ntp < 4; ntp++) {
                uint32_t ro = (uint32_t)(b_row + ntp * 16) * 128;
                uint32_t r0, r1, r2, r3;
                LDSM4(r0, r1, r2, r3, Bh_b + ro + b_off);
                bhf[2 * ntp][0] = r0; bhf[2 * ntp][1] = r1;
                bhf[2 * ntp + 1][0] = r2; bhf[2 * ntp + 1][1] = r3;
                LDSM4(r0, r1, r2, r3, Bl_b + ro + b_off);
                blf[2 * ntp][0] = r0; blf[2 * ntp][1] = r1;
                blf[2 * ntp + 1][0] = r2; blf[2 * ntp + 1][1] = r3;
            }
            // term-major ordering: no back-to-back same-accumulator MMAs
#pragma unroll
            for (int mt = 0; mt < 4; mt++)
#pragma unroll
                for (int nt = 0; nt < 8; nt++)
                    MMA16816(acc[mt][nt], ah[mt], bhf[nt]);
#pragma unroll
            for (int mt = 0; mt < 4; mt++)
#pragma unroll
                for (int nt = 0; nt < 8; nt++)
                    MMA16816(acc[mt][nt], ah[mt], blf[nt]);
#pragma unroll
            for (int mt = 0; mt < 4; mt++)
#pragma unroll
                for (int nt = 0; nt < 8; nt++)
                    MMA16816(acc[mt][nt], al[mt], bhf[nt]);
        }
        __syncthreads();
    }

    // ---- epilogue ----
    if (mode == 0) {
        int gm = m0 + warp_m * 64 + (lane >> 2);
#pragma unroll
        for (int mt = 0; mt < 4; mt++)
#pragma unroll
            for (int nt = 0; nt < 8; nt++) {
                int col = n0 + warp_n * 64 + nt * 8 + (lane & 3) * 2;
                int row = gm + mt * 16;
                float* d0 = dst + ((size_t)bh * PP + row) * PP + col;
                *(float2*)d0 = make_float2(acc[mt][nt][0], acc[mt][nt][1]);
                *(float2*)(d0 + 8 * PP) = make_float2(acc[mt][nt][2], acc[mt][nt][3]);
            }
    } else if (mode == 1) {
        int gm = m0 + warp_m * 64 + (lane >> 2);
        int b = bh >> 1, h = bh & 1;
#pragma unroll
        for (int mt = 0; mt < 4; mt++)
#pragma unroll
            for (int nt = 0; nt < 8; nt++) {
                int e = n0 + warp_n * 64 + nt * 8 + (lane & 3) * 2;
                int d = e >> 5, t = e & 31;
                int p = gm + mt * 16;
                float* d0 = dst + (((size_t)b * CC + h * DD + d) * PP + p) * TT + t;
                *(float2*)d0 = make_float2(acc[mt][nt][0], acc[mt][nt][1]);
                *(float2*)(d0 + 8 * TT) = make_float2(acc[mt][nt][2], acc[mt][nt][3]);
            }
    } else {
        // mode 2: QKV epilogue. dst = bias. kind determined by M tile.
        const float* bias = dst;
        int kind = blockIdx.y;                 // 0=q 1=k 2=v
        __nv_bfloat16* dh = (kind == 0) ? g_q_hi : (kind == 1) ? g_k_hi : g_v_hi;
        __nv_bfloat16* dl = (kind == 0) ? g_q_lo : (kind == 1) ? g_k_lo : g_v_lo;
        float mul = (kind == 0) ? 0.125f : 1.0f;
#pragma unroll
        for (int mt = 0; mt < 4; mt++)
#pragma unroll
            for (int nt = 0; nt < 8; nt++) {
                int n = n0 + warp_n * 64 + nt * 8 + (lane & 3) * 2;
                int b = n >> 14;               // / (P*T)
                int p = (n >> 5) & (PP - 1);
                int t = n & (TT - 1);
#pragma unroll
                for (int half = 0; half < 2; half++) {
                    int o = m0 + warp_m * 64 + mt * 16 + (lane >> 2) + half * 8;
                    float bv = __ldg(&bias[o]);
                    int oc = o & (CC - 1);
                    int h = oc >> 6, d = oc & (DD - 1);
                    float v0 = (acc[mt][nt][2 * half + 0] + bv) * mul;
                    float v1 = (acc[mt][nt][2 * half + 1] + bv) * mul;
                    __nv_bfloat16 h2[2], l2[2];
                    split_bf16(v0, h2[0], l2[0]);
                    split_bf16(v1, h2[1], l2[1]);
                    size_t off = (((size_t)b * HH + h) * PP + p) * EE + d * TT + t;
                    *(uint32_t*)(dh + off) = *(const uint32_t*)h2;
                    *(uint32_t*)(dl + off) = *(const uint32_t*)l2;
                }
            }
    }
}

// ---------------------------------------------------------------------------
// K3: row softmax over g_dots; emits attn as bf16 hi/lo splits.
// ---------------------------------------------------------------------------
__global__ void __launch_bounds__(128) softmax_kernel() {
    size_t row = blockIdx.x;
    const float* r = g_dots + row * PP;
    int tid = threadIdx.x;
    float4 v = ((const float4*)r)[tid];

    float m = fmaxf(fmaxf(v.x, v.y), fmaxf(v.z, v.w));
#pragma unroll
    for (int o = 16; o; o >>= 1) m = fmaxf(m, __shfl_xor_sync(0xffffffffu, m, o));
    __shared__ float red[4];
    int wid = tid >> 5;
    if ((tid & 31) == 0) red[wid] = m;
    __syncthreads();
    m = fmaxf(fmaxf(red[0], red[1]), fmaxf(red[2], red[3]));

    v.x = expf(v.x - m); v.y = expf(v.y - m);
    v.z = expf(v.z - m); v.w = expf(v.w - m);
    float s = v.x + v.y + v.z + v.w;
#pragma unroll
    for (int o = 16; o; o >>= 1) s += __shfl_xor_sync(0xffffffffu, s, o);
    __syncthreads();
    if ((tid & 31) == 0) red[wid] = s;
    __syncthreads();
    float inv = 1.0f / (red[0] + red[1] + red[2] + red[3]);
    v.x *= inv; v.y *= inv; v.z *= inv; v.w *= inv;

    __nv_bfloat16 hi[4], lo[4];
    split_bf16(v.x, hi[0], lo[0]); split_bf16(v.y, hi[1], lo[1]);
    split_bf16(v.z, hi[2], lo[2]); split_bf16(v.w, hi[3], lo[3]);
    *(uint2*)(g_attn_hi + row * PP + tid * 4) = *(const uint2*)hi;
    *(uint2*)(g_attn_lo + row * PP + tid * 4) = *(const uint2*)lo;
}

// ---------------------------------------------------------------------------
extern "C" void kernel_launch(void* const* d_in, const int* in_sizes, int n_in,
                              void* d_out, int out_size) {
    const float* x = (const float*)d_in[0];
    const float* W = (const float*)d_in[1];
    const float* b = (const float*)d_in[2];
    float* out = (float*)d_out;

    cudaFuncSetAttribute(mma_nt_kernel, cudaFuncAttributeMaxDynamicSharedMemorySize, MMA_SMEM_REQ);

    wsplit_kernel<<<(O3 * CC + 255) / 256, 256>>>(W);
    xsplit_kernel<<<dim3(CC / 32, PP, BB), dim3(32, 8)>>>(x);

    // QKV: D[384, 262144] = W @ xT^T, K=128, mode 2
    {
        __nv_bfloat16 *wh, *wl, *xh, *xl;
        cudaGetSymbolAddress((void**)&wh, g_w_hi);
        cudaGetSymbolAddress((void**)&wl, g_w_lo);
        cudaGetSymbolAddress((void**)&xh, g_xt_hi);
        cudaGetSymbolAddress((void**)&xl, g_xt_lo);
        dim3 g((unsigned)(NN / 256), O3 / 128, 1);
        mma_nt_kernel<<<g, 256, MMA_SMEM_REQ>>>(wh, wl, xh, xl, CC,
                                                0, 0, 2, (float*)b);
    }

    vt_kernel<<<dim3(EE / 64, PP / 64, BB * HH), 256>>>();

    // dots = Qs @ K^T : M=512, N=512, K=2048
    {
        float* dots = nullptr;
        cudaGetSymbolAddress((void**)&dots, g_dots);
        __nv_bfloat16 *qh, *ql, *kh, *kl;
        cudaGetSymbolAddress((void**)&qh, g_q_hi);
        cudaGetSymbolAddress((void**)&ql, g_q_lo);
        cudaGetSymbolAddress((void**)&kh, g_k_hi);
        cudaGetSymbolAddress((void**)&kl, g_k_lo);
        dim3 g(PP / 256, PP / 128, BB * HH);
        mma_nt_kernel<<<g, 256, MMA_SMEM_REQ>>>(qh, ql, kh, kl, EE,
                                                (size_t)PP * EE, (size_t)PP * EE, 0, dots);
    }

    softmax_kernel<<<BB * HH * PP, 128>>>();

    // out = attn @ V : M=512, N=2048(E), K=512
    {
        __nv_bfloat16 *ah, *al, *vh, *vl;
        cudaGetSymbolAddress((void**)&ah, g_attn_hi);
        cudaGetSymbolAddress((void**)&al, g_attn_lo);
        cudaGetSymbolAddress((void**)&vh, g_vt_hi);
        cudaGetSymbolAddress((void**)&vl, g_vt_lo);
        dim3 g(EE / 256, PP / 128, BB * HH);
        mma_nt_kernel<<<g, 256, MMA_SMEM_REQ>>>(ah, al, vh, vl, PP,
                                                (size_t)PP * PP, (size_t)EE * PP, 1, out);
    }
}

// round 6
// speedup vs baseline: 2.9660x; 1.0596x over previous
#include <cuda_runtime.h>
#include <cuda_bf16.h>
#include <cstdint>

// Problem constants
#define BB 16
#define CC 128
#define PP 512
#define TT 32
#define HH 2
#define DD 64
#define EE (DD * TT)   // 2048
#define O3 (3 * CC)    // 384
#define NN ((size_t)BB * PP * TT)   // 262144 columns of the QKV GEMM

// ======================== mma.sync helpers ========================
static __device__ __forceinline__ uint32_t smem_u32(const void* p) {
    uint32_t a;
    asm("{ .reg .u64 t; cvta.to.shared.u64 t, %1; cvt.u32.u64 %0, t; }" : "=r"(a) : "l"(p));
    return a;
}
#define LDSM4(r0, r1, r2, r3, a) \
    asm volatile("ldmatrix.sync.aligned.m8n8.x4.shared.b16 {%0,%1,%2,%3}, [%4];" \
        : "=r"(r0), "=r"(r1), "=r"(r2), "=r"(r3) : "r"(a))
#define LDSM4T(r0, r1, r2, r3, a) \
    asm volatile("ldmatrix.sync.aligned.m8n8.x4.trans.shared.b16 {%0,%1,%2,%3}, [%4];" \
        : "=r"(r0), "=r"(r1), "=r"(r2), "=r"(r3) : "r"(a))
#define MMA16816(d, a, b) \
    asm volatile("mma.sync.aligned.m16n8k16.row.col.f32.bf16.bf16.f32 " \
        "{%0,%1,%2,%3}, {%4,%5,%6,%7}, {%8,%9}, {%0,%1,%2,%3};" \
        : "+f"((d)[0]), "+f"((d)[1]), "+f"((d)[2]), "+f"((d)[3]) \
        : "r"((a)[0]), "r"((a)[1]), "r"((a)[2]), "r"((a)[3]), "r"((b)[0]), "r"((b)[1]))
#define CP_ASYNC16(s, g) \
    asm volatile("cp.async.cg.shared.global [%0], [%1], 16;" :: "r"(s), "l"(g) : "memory")
#define CP_COMMIT() asm volatile("cp.async.commit_group;" ::: "memory")

// ======================== scratch (device globals) ========================
__device__ __nv_bfloat16 g_w_hi[O3 * CC];
__device__ __nv_bfloat16 g_w_lo[O3 * CC];
__device__ __nv_bfloat16 g_xt_hi[NN * CC];    // [n=(b,p,t)][c]
__device__ __nv_bfloat16 g_xt_lo[NN * CC];
__device__ __nv_bfloat16 g_q_hi[(size_t)BB * HH * PP * EE];
__device__ __nv_bfloat16 g_q_lo[(size_t)BB * HH * PP * EE];
__device__ __nv_bfloat16 g_k_hi[(size_t)BB * HH * PP * EE];
__device__ __nv_bfloat16 g_k_lo[(size_t)BB * HH * PP * EE];
__device__ __nv_bfloat16 g_v_hi[(size_t)BB * HH * PP * EE];   // [bh][q][e] natural
__device__ __nv_bfloat16 g_v_lo[(size_t)BB * HH * PP * EE];
__device__ float         g_dots[(size_t)BB * HH * PP * PP];
__device__ __nv_bfloat16 g_attn_hi[(size_t)BB * HH * PP * PP];
__device__ __nv_bfloat16 g_attn_lo[(size_t)BB * HH * PP * PP];

static __device__ __forceinline__ void split_bf16(float v, __nv_bfloat16& hi, __nv_bfloat16& lo) {
    hi = __float2bfloat16(v);
    lo = __float2bfloat16(v - __bfloat162float(hi));
}

// ---------------------------------------------------------------------------
// K0: split W -> bf16 hi/lo (already K-major: [o][c], c contiguous)
// ---------------------------------------------------------------------------
__global__ void wsplit_kernel(const float* __restrict__ W) {
    int i = blockIdx.x * blockDim.x + threadIdx.x;
    if (i < O3 * CC) split_bf16(W[i], g_w_hi[i], g_w_lo[i]);
}

// ---------------------------------------------------------------------------
// K1: transpose + split x (B,C,P,T) fp32 -> xT bf16 hi/lo [(b,p,t)][c]
// v2: hi|lo packed uint32 smem words, uint4 global stores.
// ---------------------------------------------------------------------------
__global__ void __launch_bounds__(256) xsplit_kernel(const float* __restrict__ x) {
    __shared__ uint32_t tile[32][129];   // [t][c], pitch 129 words
    int p = blockIdx.x, b = blockIdx.y;
    int tid = threadIdx.x;

    const float* src = x + ((size_t)b * CC * PP + p) * TT;
#pragma unroll
    for (int i = 0; i < 4; i++) {
        int idx = tid + i * 256;
        int c = idx >> 3, t4 = idx & 7;
        float4 v = *(const float4*)(src + (size_t)c * PP * TT + t4 * 4);
        float vv[4] = {v.x, v.y, v.z, v.w};
#pragma unroll
        for (int k = 0; k < 4; k++) {
            __nv_bfloat16 hi, lo;
            split_bf16(vv[k], hi, lo);
            tile[t4 * 4 + k][c] =
                (uint32_t)*(const uint16_t*)&hi | ((uint32_t)*(const uint16_t*)&lo << 16);
        }
    }
    __syncthreads();

    size_t nbase = ((size_t)b * PP + p) * TT;
#pragma unroll
    for (int i = 0; i < 2; i++) {
        int idx = tid + i * 256;
        int t = idx >> 4, c8 = idx & 15;
        uint16_t h[8], l[8];
#pragma unroll
        for (int k = 0; k < 8; k++) {
            uint32_t w = tile[t][c8 * 8 + k];
            h[k] = (uint16_t)w;
            l[k] = (uint16_t)(w >> 16);
        }
        size_t off = (nbase + t) * CC + c8 * 8;
        *(uint4*)(g_xt_hi + off) = *(const uint4*)h;
        *(uint4*)(g_xt_lo + off) = *(const uint4*)l;
    }
}

// ---------------------------------------------------------------------------
// Generic GEMM via mma.sync bf16 3-split, fp32 accum, 2-stage cp.async.
// D[M,N] = A[M,K] @ B^T per blockIdx.z. Block tile 128x256, Ktile 64.
// 256 threads = 8 warps (2x4), warp tile 64x64 = 4x8 m16n8k16, term-major MMA.
// transB=0: B is [N][K] k-major (NT GEMM).
// transB=1: B is [K][N] n-major (NN GEMM) — loaded via ldmatrix.trans.
// mode 0: fp32 dots out. mode 1: scatter to output (B,C,P,T).
// mode 2: QKV epilogue — +bias (dst = bias ptr), q-scale, split-store q/k/v.
// ---------------------------------------------------------------------------
#define STAGE_BYTES (96 * 1024)
#define MMA_SMEM_REQ (2 * STAGE_BYTES + 1024)

__global__ void __launch_bounds__(256, 1) mma_nt_kernel(
    const __nv_bfloat16* __restrict__ Ah, const __nv_bfloat16* __restrict__ Al,
    const __nv_bfloat16* __restrict__ Bh, const __nv_bfloat16* __restrict__ Bl,
    int Kdim, int bLd, int transB, size_t aStride, size_t bStride,
    int mode, float* __restrict__ dst)
{
    extern __shared__ char smem[];
    uint32_t base = (smem_u32(smem) + 1023) & ~1023u;

    int tid = threadIdx.x;
    int wid = tid >> 5, lane = tid & 31;
    int bh = blockIdx.z;
    int m0 = blockIdx.y * 128;
    int n0 = blockIdx.x * 256;

    const __nv_bfloat16* A0h = Ah + (size_t)bh * aStride;
    const __nv_bfloat16* A0l = Al + (size_t)bh * aStride;
    const __nv_bfloat16* B0h = Bh + (size_t)bh * bStride;
    const __nv_bfloat16* B0l = Bl + (size_t)bh * bStride;

    // ---- async tile loader: A (2x16KB) + B (2x32KB) into stage (it&1) ----
    auto load_tiles = [&](int it) {
        int kk = it * 64;
        uint32_t db = base + (uint32_t)(it & 1) * STAGE_BYTES;
#pragma unroll
        for (int i = 0; i < 8; i++) {                    // A hi/lo: 128 rows x 128B
            const int tile = i >> 2;
            int c = tid + i * 256;
            int r = (c >> 3) & 127;
            int j = c & 7;
            const __nv_bfloat16* g = (tile ? A0l : A0h)
                + (size_t)(m0 + r) * Kdim + (kk + j * 8);
            uint32_t s = db + tile * 16384 + r * 128 + ((j * 16) ^ ((r & 7) << 4));
            CP_ASYNC16(s, g);
        }
        if (!transB) {
#pragma unroll
            for (int i = 0; i < 16; i++) {               // B hi/lo: 256 n-rows x 128B
                const int tile = i >> 3;
                int c = tid + i * 256;
                int r = (c >> 3) & 255;
                int j = c & 7;
                const __nv_bfloat16* g = (tile ? B0l : B0h)
                    + (size_t)(n0 + r) * bLd + (kk + j * 8);
                uint32_t s = db + 32768 + tile * 32768 + r * 128 + ((j * 16) ^ ((r & 7) << 4));
                CP_ASYNC16(s, g);
            }
        } else {
#pragma unroll
            for (int i = 0; i < 16; i++) {               // B hi/lo: 64 k-rows x 512B
                const int tile = i >> 3;
                int c = tid + (i & 7) * 256;
                int r = (c >> 5) & 63;
                int j = c & 31;
                const __nv_bfloat16* g = (tile ? B0l : B0h)
                    + (size_t)(kk + r) * bLd + (n0 + j * 8);
                uint32_t s = db + 32768 + tile * 32768 + r * 512 + ((j * 16) ^ ((r & 7) << 4));
                CP_ASYNC16(s, g);
            }
        }
        CP_COMMIT();
    };

    // warp coordinates: 2 (m) x 4 (n) warps, warp tile 64x64
    int warp_m = wid & 1, warp_n = wid >> 1;
    int row_in = lane & 7, mat = lane >> 3;
    uint32_t xorv = (uint32_t)row_in << 4;
    int a_row = warp_m * 64 + (mat & 1) * 8 + row_in;    // + mt*16
    int a_khalf = (mat >> 1) * 16;
    int b_row = warp_n * 64 + (mat >> 1) * 8 + row_in;   // + ntp*16  (non-trans)
    int b_khalf = (mat & 1) * 16;
    // trans-B addressing: krow within k-16-block, e16 chunk column
    int t_krow_in = (mat & 1) * 8 + row_in;
    uint32_t t_cbase = (uint32_t)(warp_n * 128 + (mat >> 1) * 16);

    float acc[4][8][4];
#pragma unroll
    for (int i = 0; i < 4; i++)
#pragma unroll
        for (int j = 0; j < 8; j++)
#pragma unroll
            for (int k = 0; k < 4; k++) acc[i][j][k] = 0.f;

    int iters = Kdim / 64;
    load_tiles(0);

    for (int it = 0; it < iters; it++) {
        if (it + 1 < iters) {
            load_tiles(it + 1);
            asm volatile("cp.async.wait_group 1;" ::: "memory");
        } else {
            asm volatile("cp.async.wait_group 0;" ::: "memory");
        }
        __syncthreads();

        uint32_t db = base + (uint32_t)(it & 1) * STAGE_BYTES;
        uint32_t Ah_b = db, Al_b = db + 16384, Bh_b = db + 32768, Bl_b = db + 65536;

#pragma unroll
        for (int kq = 0; kq < 4; kq++) {
            uint32_t ah[4][4], al[4][4], bhf[8][2], blf[8][2];
            uint32_t a_off = (uint32_t)((kq * 32 + a_khalf) ^ (int)xorv);

            // --- A-hi + B-hi fragments, then term1 ---
#pragma unroll
            for (int mt = 0; mt < 4; mt++) {
                uint32_t ro = (uint32_t)(a_row + mt * 16) * 128;
                LDSM4(ah[mt][0], ah[mt][1], ah[mt][2], ah[mt][3], Ah_b + ro + a_off);
            }
            if (!transB) {
                uint32_t b_off = (uint32_t)((kq * 32 + b_khalf) ^ (int)xorv);
#pragma unroll
                for (int ntp = 0; ntp < 4; ntp++) {
                    uint32_t ro = (uint32_t)(b_row + ntp * 16) * 128;
                    uint32_t r0, r1, r2, r3;
                    LDSM4(r0, r1, r2, r3, Bh_b + ro + b_off);
                    bhf[2 * ntp][0] = r0; bhf[2 * ntp][1] = r1;
                    bhf[2 * ntp + 1][0] = r2; bhf[2 * ntp + 1][1] = r3;
                }
            } else {
                int krow = kq * 16 + t_krow_in;
                uint32_t rbase = (uint32_t)krow * 512;
                uint32_t sw = (uint32_t)((krow & 7) << 4);
#pragma unroll
                for (int ntp = 0; ntp < 4; ntp++) {
                    uint32_t co = (t_cbase + ntp * 32) ^ sw;
                    uint32_t r0, r1, r2, r3;
                    LDSM4T(r0, r1, r2, r3, Bh_b + rbase + co);
                    bhf[2 * ntp][0] = r0; bhf[2 * ntp][1] = r1;
                    bhf[2 * ntp + 1][0] = r2; bhf[2 * ntp + 1][1] = r3;
                }
            }
#pragma unroll
            for (int mt = 0; mt < 4; mt++)
#pragma unroll
                for (int nt = 0; nt < 8; nt++)
                    MMA16816(acc[mt][nt], ah[mt], bhf[nt]);

            // --- B-lo fragments, term2 ---
            if (!transB) {
                uint32_t b_off = (uint32_t)((kq * 32 + b_khalf) ^ (int)xorv);
#pragma unroll
                for (int ntp = 0; ntp < 4; ntp++) {
                    uint32_t ro = (uint32_t)(b_row + ntp * 16) * 128;
                    uint32_t r0, r1, r2, r3;
                    LDSM4(r0, r1, r2, r3, Bl_b + ro + b_off);
                    blf[2 * ntp][0] = r0; blf[2 * ntp][1] = r1;
                    blf[2 * ntp + 1][0] = r2; blf[2 * ntp + 1][1] = r3;
                }
            } else {
                int krow = kq * 16 + t_krow_in;
                uint32_t rbase = (uint32_t)krow * 512;
                uint32_t sw = (uint32_t)((krow & 7) << 4);
#pragma unroll
                for (int ntp = 0; ntp < 4; ntp++) {
                    uint32_t co = (t_cbase + ntp * 32) ^ sw;
                    uint32_t r0, r1, r2, r3;
                    LDSM4T(r0, r1, r2, r3, Bl_b + rbase + co);
                    blf[2 * ntp][0] = r0; blf[2 * ntp][1] = r1;
                    blf[2 * ntp + 1][0] = r2; blf[2 * ntp + 1][1] = r3;
                }
            }
#pragma unroll
            for (int mt = 0; mt < 4; mt++)
#pragma unroll
                for (int nt = 0; nt < 8; nt++)
                    MMA16816(acc[mt][nt], ah[mt], blf[nt]);

            // --- A-lo fragments, term3 ---
#pragma unroll
            for (int mt = 0; mt < 4; mt++) {
                uint32_t ro = (uint32_t)(a_row + mt * 16) * 128;
                LDSM4(al[mt][0], al[mt][1], al[mt][2], al[mt][3], Al_b + ro + a_off);
            }
#pragma unroll
            for (int mt = 0; mt < 4; mt++)
#pragma unroll
                for (int nt = 0; nt < 8; nt++)
                    MMA16816(acc[mt][nt], al[mt], bhf[nt]);
        }
        __syncthreads();
    }

    // ---- epilogue ----
    if (mode == 0) {
        int gm = m0 + warp_m * 64 + (lane >> 2);
#pragma unroll
        for (int mt = 0; mt < 4; mt++)
#pragma unroll
            for (int nt = 0; nt < 8; nt++) {
                int col = n0 + warp_n * 64 + nt * 8 + (lane & 3) * 2;
                int row = gm + mt * 16;
                float* d0 = dst + ((size_t)bh * PP + row) * PP + col;
                *(float2*)d0 = make_float2(acc[mt][nt][0], acc[mt][nt][1]);
                *(float2*)(d0 + 8 * PP) = make_float2(acc[mt][nt][2], acc[mt][nt][3]);
            }
    } else if (mode == 1) {
        int gm = m0 + warp_m * 64 + (lane >> 2);
        int b = bh >> 1, h = bh & 1;
#pragma unroll
        for (int mt = 0; mt < 4; mt++)
#pragma unroll
            for (int nt = 0; nt < 8; nt++) {
                int e = n0 + warp_n * 64 + nt * 8 + (lane & 3) * 2;
                int d = e >> 5, t = e & 31;
                int p = gm + mt * 16;
                float* d0 = dst + (((size_t)b * CC + h * DD + d) * PP + p) * TT + t;
                *(float2*)d0 = make_float2(acc[mt][nt][0], acc[mt][nt][1]);
                *(float2*)(d0 + 8 * TT) = make_float2(acc[mt][nt][2], acc[mt][nt][3]);
            }
    } else {
        // mode 2: QKV epilogue. dst = bias. kind determined by M tile.
        const float* bias = dst;
        int kind = blockIdx.y;                 // 0=q 1=k 2=v
        __nv_bfloat16* dh = (kind == 0) ? g_q_hi : (kind == 1) ? g_k_hi : g_v_hi;
        __nv_bfloat16* dl = (kind == 0) ? g_q_lo : (kind == 1) ? g_k_lo : g_v_lo;
        float mul = (kind == 0) ? 0.125f : 1.0f;
#pragma unroll
        for (int mt = 0; mt < 4; mt++)
#pragma unroll
            for (int nt = 0; nt < 8; nt++) {
                int n = n0 + warp_n * 64 + nt * 8 + (lane & 3) * 2;
                int b = n >> 14;               // / (P*T)
                int p = (n >> 5) & (PP - 1);
                int t = n & (TT - 1);
#pragma unroll
                for (int half = 0; half < 2; half++) {
                    int o = m0 + warp_m * 64 + mt * 16 + (lane >> 2) + half * 8;
                    float bv = __ldg(&bias[o]);
                    int oc = o & (CC - 1);
                    int h = oc >> 6, d = oc & (DD - 1);
                    float v0 = (acc[mt][nt][2 * half + 0] + bv) * mul;
                    float v1 = (acc[mt][nt][2 * half + 1] + bv) * mul;
                    __nv_bfloat16 h2[2], l2[2];
                    split_bf16(v0, h2[0], l2[0]);
                    split_bf16(v1, h2[1], l2[1]);
                    size_t off = (((size_t)b * HH + h) * PP + p) * EE + d * TT + t;
                    *(uint32_t*)(dh + off) = *(const uint32_t*)h2;
                    *(uint32_t*)(dl + off) = *(const uint32_t*)l2;
                }
            }
    }
}

// ---------------------------------------------------------------------------
// K3: row softmax over g_dots; emits attn as bf16 hi/lo splits.
// ---------------------------------------------------------------------------
__global__ void __launch_bounds__(128) softmax_kernel() {
    size_t row = blockIdx.x;
    const float* r = g_dots + row * PP;
    int tid = threadIdx.x;
    float4 v = ((const float4*)r)[tid];

    float m = fmaxf(fmaxf(v.x, v.y), fmaxf(v.z, v.w));
#pragma unroll
    for (int o = 16; o; o >>= 1) m = fmaxf(m, __shfl_xor_sync(0xffffffffu, m, o));
    __shared__ float red[4];
    int wid = tid >> 5;
    if ((tid & 31) == 0) red[wid] = m;
    __syncthreads();
    m = fmaxf(fmaxf(red[0], red[1]), fmaxf(red[2], red[3]));

    v.x = expf(v.x - m); v.y = expf(v.y - m);
    v.z = expf(v.z - m); v.w = expf(v.w - m);
    float s = v.x + v.y + v.z + v.w;
#pragma unroll
    for (int o = 16; o; o >>= 1) s += __shfl_xor_sync(0xffffffffu, s, o);
    __syncthreads();
    if ((tid & 31) == 0) red[wid] = s;
    __syncthreads();
    float inv = 1.0f / (red[0] + red[1] + red[2] + red[3]);
    v.x *= inv; v.y *= inv; v.z *= inv; v.w *= inv;

    __nv_bfloat16 hi[4], lo[4];
    split_bf16(v.x, hi[0], lo[0]); split_bf16(v.y, hi[1], lo[1]);
    split_bf16(v.z, hi[2], lo[2]); split_bf16(v.w, hi[3], lo[3]);
    *(uint2*)(g_attn_hi + row * PP + tid * 4) = *(const uint2*)hi;
    *(uint2*)(g_attn_lo + row * PP + tid * 4) = *(const uint2*)lo;
}

// ---------------------------------------------------------------------------
extern "C" void kernel_launch(void* const* d_in, const int* in_sizes, int n_in,
                              void* d_out, int out_size) {
    const float* x = (const float*)d_in[0];
    const float* W = (const float*)d_in[1];
    const float* b = (const float*)d_in[2];
    float* out = (float*)d_out;

    cudaFuncSetAttribute(mma_nt_kernel, cudaFuncAttributeMaxDynamicSharedMemorySize, MMA_SMEM_REQ);

    wsplit_kernel<<<(O3 * CC + 255) / 256, 256>>>(W);
    xsplit_kernel<<<dim3(PP, BB), 256>>>(x);

    // QKV: D[384, 262144] = W @ xT^T, K=128, NT, mode 2
    {
        __nv_bfloat16 *wh, *wl, *xh, *xl;
        cudaGetSymbolAddress((void**)&wh, g_w_hi);
        cudaGetSymbolAddress((void**)&wl, g_w_lo);
        cudaGetSymbolAddress((void**)&xh, g_xt_hi);
        cudaGetSymbolAddress((void**)&xl, g_xt_lo);
        dim3 g((unsigned)(NN / 256), O3 / 128, 1);
        mma_nt_kernel<<<g, 256, MMA_SMEM_REQ>>>(wh, wl, xh, xl, CC, CC, 0,
                                                0, 0, 2, (float*)b);
    }

    // dots = Qs @ K^T : M=512, N=512, K=2048, NT, mode 0
    {
        float* dots = nullptr;
        cudaGetSymbolAddress((void**)&dots, g_dots);
        __nv_bfloat16 *qh, *ql, *kh, *kl;
        cudaGetSymbolAddress((void**)&qh, g_q_hi);
        cudaGetSymbolAddress((void**)&ql, g_q_lo);
        cudaGetSymbolAddress((void**)&kh, g_k_hi);
        cudaGetSymbolAddress((void**)&kl, g_k_lo);
        dim3 g(PP / 256, PP / 128, BB * HH);
        mma_nt_kernel<<<g, 256, MMA_SMEM_REQ>>>(qh, ql, kh, kl, EE, EE, 0,
                                                (size_t)PP * EE, (size_t)PP * EE, 0, dots);
    }

    softmax_kernel<<<BB * HH * PP, 128>>>();

    // out = attn @ V : M=512, N=2048(E), K=512, NN (trans-B), mode 1
    {
        __nv_bfloat16 *ah, *al, *vh, *vl;
        cudaGetSymbolAddress((void**)&ah, g_attn_hi);
        cudaGetSymbolAddress((void**)&al, g_attn_lo);
        cudaGetSymbolAddress((void**)&vh, g_v_hi);
        cudaGetSymbolAddress((void**)&vl, g_v_lo);
        dim3 g(EE / 256, PP / 128, BB * HH);
        mma_nt_kernel<<<g, 256, MMA_SMEM_REQ>>>(ah, al, vh, vl, PP, EE, 1,
                                                (size_t)PP * PP, (size_t)PP * EE, 1, out);
    }
}

// round 7
// speedup vs baseline: 3.1116x; 1.0491x over previous
#include <cuda_runtime.h>
#include <cuda_bf16.h>
#include <cstdint>

// Problem constants
#define BB 16
#define CC 128
#define PP 512
#define TT 32
#define HH 2
#define DD 64
#define EE (DD * TT)   // 2048
#define O3 (3 * CC)    // 384
#define NN ((size_t)BB * PP * TT)   // 262144 columns of the QKV GEMM

// ======================== mma.sync helpers ========================
static __device__ __forceinline__ uint32_t smem_u32(const void* p) {
    uint32_t a;
    asm("{ .reg .u64 t; cvta.to.shared.u64 t, %1; cvt.u32.u64 %0, t; }" : "=r"(a) : "l"(p));
    return a;
}
#define LDSM4(r0, r1, r2, r3, a) \
    asm volatile("ldmatrix.sync.aligned.m8n8.x4.shared.b16 {%0,%1,%2,%3}, [%4];" \
        : "=r"(r0), "=r"(r1), "=r"(r2), "=r"(r3) : "r"(a))
#define LDSM4T(r0, r1, r2, r3, a) \
    asm volatile("ldmatrix.sync.aligned.m8n8.x4.trans.shared.b16 {%0,%1,%2,%3}, [%4];" \
        : "=r"(r0), "=r"(r1), "=r"(r2), "=r"(r3) : "r"(a))
#define MMA16816(d, a, b) \
    asm volatile("mma.sync.aligned.m16n8k16.row.col.f32.bf16.bf16.f32 " \
        "{%0,%1,%2,%3}, {%4,%5,%6,%7}, {%8,%9}, {%0,%1,%2,%3};" \
        : "+f"((d)[0]), "+f"((d)[1]), "+f"((d)[2]), "+f"((d)[3]) \
        : "r"((a)[0]), "r"((a)[1]), "r"((a)[2]), "r"((a)[3]), "r"((b)[0]), "r"((b)[1]))
#define CP_ASYNC16(s, g) \
    asm volatile("cp.async.cg.shared.global [%0], [%1], 16;" :: "r"(s), "l"(g) : "memory")
#define CP_COMMIT() asm volatile("cp.async.commit_group;" ::: "memory")

// ======================== scratch (device globals) ========================
__device__ __nv_bfloat16 g_w_hi[O3 * CC];
__device__ __nv_bfloat16 g_w_lo[O3 * CC];
__device__ __nv_bfloat16 g_xt_hi[NN * CC];    // [n=(b,p,t)][c]
__device__ __nv_bfloat16 g_xt_lo[NN * CC];
__device__ __nv_bfloat16 g_q_hi[(size_t)BB * HH * PP * EE];
__device__ __nv_bfloat16 g_q_lo[(size_t)BB * HH * PP * EE];
__device__ __nv_bfloat16 g_k_hi[(size_t)BB * HH * PP * EE];
__device__ __nv_bfloat16 g_k_lo[(size_t)BB * HH * PP * EE];
__device__ __nv_bfloat16 g_v_hi[(size_t)BB * HH * PP * EE];   // [bh][q][e] natural
__device__ __nv_bfloat16 g_v_lo[(size_t)BB * HH * PP * EE];
__device__ float         g_dots[(size_t)BB * HH * PP * PP];
__device__ __nv_bfloat16 g_attn_hi[(size_t)BB * HH * PP * PP];
__device__ __nv_bfloat16 g_attn_lo[(size_t)BB * HH * PP * PP];

static __device__ __forceinline__ void split_bf16(float v, __nv_bfloat16& hi, __nv_bfloat16& lo) {
    hi = __float2bfloat16(v);
    lo = __float2bfloat16(v - __bfloat162float(hi));
}

// ---------------------------------------------------------------------------
// K0: split W -> bf16 hi/lo (already K-major: [o][c], c contiguous)
// ---------------------------------------------------------------------------
__global__ void wsplit_kernel(const float* __restrict__ W) {
    int i = blockIdx.x * blockDim.x + threadIdx.x;
    if (i < O3 * CC) split_bf16(W[i], g_w_hi[i], g_w_lo[i]);
}

// ---------------------------------------------------------------------------
// K1: transpose + split x (B,C,P,T) fp32 -> xT bf16 hi/lo [(b,p,t)][c]
// ---------------------------------------------------------------------------
__global__ void __launch_bounds__(256) xsplit_kernel(const float* __restrict__ x) {
    __shared__ uint32_t tile[32][129];   // [t][c], pitch 129 words
    int p = blockIdx.x, b = blockIdx.y;
    int tid = threadIdx.x;

    const float* src = x + ((size_t)b * CC * PP + p) * TT;
#pragma unroll
    for (int i = 0; i < 4; i++) {
        int idx = tid + i * 256;
        int c = idx >> 3, t4 = idx & 7;
        float4 v = *(const float4*)(src + (size_t)c * PP * TT + t4 * 4);
        float vv[4] = {v.x, v.y, v.z, v.w};
#pragma unroll
        for (int k = 0; k < 4; k++) {
            __nv_bfloat16 hi, lo;
            split_bf16(vv[k], hi, lo);
            tile[t4 * 4 + k][c] =
                (uint32_t)*(const uint16_t*)&hi | ((uint32_t)*(const uint16_t*)&lo << 16);
        }
    }
    __syncthreads();

    size_t nbase = ((size_t)b * PP + p) * TT;
#pragma unroll
    for (int i = 0; i < 2; i++) {
        int idx = tid + i * 256;
        int t = idx >> 4, c8 = idx & 15;
        uint16_t h[8], l[8];
#pragma unroll
        for (int k = 0; k < 8; k++) {
            uint32_t w = tile[t][c8 * 8 + k];
            h[k] = (uint16_t)w;
            l[k] = (uint16_t)(w >> 16);
        }
        size_t off = (nbase + t) * CC + c8 * 8;
        *(uint4*)(g_xt_hi + off) = *(const uint4*)h;
        *(uint4*)(g_xt_lo + off) = *(const uint4*)l;
    }
}

// ---------------------------------------------------------------------------
// Generic GEMM via mma.sync bf16 3-split, fp32 accum.
// Block tile 128x128, K-tile 32, 3-stage cp.async ring (96 KB), 2 CTAs/SM.
// 256 threads = 8 warps (2m x 4n), warp tile 64x32 = 4x4 m16n8k16.
// smem rows: 64B (NT tiles) with swizzle j ^= (r>>1)&3; trans-B tiles are
// 32 k-rows x 256B with swizzle j ^= r&7. All conflict-free for ldmatrix.
// transB=0: B is [N][K] k-major.  transB=1: B is [K][N] n-major (ldsm.trans).
// mode 0: fp32 out. mode 1: scatter to (B,C,P,T). mode 2: QKV epilogue.
// ---------------------------------------------------------------------------
#define KT 32
#define STAGE_BYTES 32768
#define MMA_SMEM_REQ (3 * STAGE_BYTES + 1024)

__global__ void __launch_bounds__(256, 2) mma_nt_kernel(
    const __nv_bfloat16* __restrict__ Ah, const __nv_bfloat16* __restrict__ Al,
    const __nv_bfloat16* __restrict__ Bh, const __nv_bfloat16* __restrict__ Bl,
    int Kdim, int bLd, int transB, size_t aStride, size_t bStride,
    int mode, float* __restrict__ dst)
{
    extern __shared__ char smem[];
    uint32_t base = (smem_u32(smem) + 1023) & ~1023u;

    int tid = threadIdx.x;
    int wid = tid >> 5, lane = tid & 31;
    int bh = blockIdx.z;
    int m0 = blockIdx.y * 128;
    int n0 = blockIdx.x * 128;

    const __nv_bfloat16* A0h = Ah + (size_t)bh * aStride;
    const __nv_bfloat16* A0l = Al + (size_t)bh * aStride;
    const __nv_bfloat16* B0h = Bh + (size_t)bh * bStride;
    const __nv_bfloat16* B0l = Bl + (size_t)bh * bStride;

    // ---- loader: A hi/lo (2x8KB) + B hi/lo (2x8KB) into stage it%3 ----
    auto load_tiles = [&](int it) {
        int kk = it * KT;
        uint32_t db = base + (uint32_t)(it % 3) * STAGE_BYTES;
        // A: 128 rows x 64B, swizzle j ^ ((r>>1)&3)
#pragma unroll
        for (int i = 0; i < 4; i++) {
            const int tile = i >> 1;
            int c = tid + (i & 1) * 256;
            int r = (c >> 2) & 127;
            int j = c & 3;
            const __nv_bfloat16* g = (tile ? A0l : A0h)
                + (size_t)(m0 + r) * Kdim + (kk + j * 8);
            uint32_t s = db + tile * 8192 + r * 64 + (((j ^ ((r >> 1) & 3))) << 4);
            CP_ASYNC16(s, g);
        }
        if (!transB) {
#pragma unroll
            for (int i = 0; i < 4; i++) {
                const int tile = i >> 1;
                int c = tid + (i & 1) * 256;
                int r = (c >> 2) & 127;
                int j = c & 3;
                const __nv_bfloat16* g = (tile ? B0l : B0h)
                    + (size_t)(n0 + r) * bLd + (kk + j * 8);
                uint32_t s = db + 16384 + tile * 8192 + r * 64 + (((j ^ ((r >> 1) & 3))) << 4);
                CP_ASYNC16(s, g);
            }
        } else {
            // B: 32 k-rows x 256B, swizzle j ^ (r&7)
#pragma unroll
            for (int i = 0; i < 4; i++) {
                const int tile = i >> 1;
                int c = tid + (i & 1) * 256;
                int r = (c >> 4) & 31;
                int j = c & 15;
                const __nv_bfloat16* g = (tile ? B0l : B0h)
                    + (size_t)(kk + r) * bLd + (n0 + j * 8);
                uint32_t s = db + 16384 + tile * 8192 + r * 256 + (((j ^ (r & 7))) << 4);
                CP_ASYNC16(s, g);
            }
        }
        CP_COMMIT();
    };

    // warp coordinates: 2 (m) x 4 (n) warps, warp tile 64x32
    int warp_m = wid & 1, warp_n = wid >> 1;
    int row_in = lane & 7, mat = lane >> 3;
    int a_row = warp_m * 64 + (mat & 1) * 8 + row_in;    // + mt*16
    uint32_t a_salt = (uint32_t)((a_row >> 1) & 3);
    int a_jk = (mat >> 1);                               // + kq*2
    int b_row = warp_n * 32 + (mat >> 1) * 8 + row_in;   // + ntp*16 (NT)
    uint32_t b_salt = (uint32_t)((b_row >> 1) & 3);
    int b_jk = (mat & 1);
    // trans-B: krow = kq*16 + t_krow_in, chunk = t_jbase + ntp*2
    int t_krow_in = (mat & 1) * 8 + row_in;
    int t_jbase = warp_n * 4 + (mat >> 1);

    float acc[4][4][4];
#pragma unroll
    for (int i = 0; i < 4; i++)
#pragma unroll
        for (int j = 0; j < 4; j++)
#pragma unroll
            for (int k = 0; k < 4; k++) acc[i][j][k] = 0.f;

    int iters = Kdim / KT;
    load_tiles(0);
    if (iters > 1) load_tiles(1);

    for (int it = 0; it < iters; it++) {
        if (it + 1 < iters) {
            asm volatile("cp.async.wait_group 1;" ::: "memory");
        } else {
            asm volatile("cp.async.wait_group 0;" ::: "memory");
        }
        __syncthreads();                 // also fences stage reuse
        if (it + 2 < iters) load_tiles(it + 2);

        uint32_t db = base + (uint32_t)(it % 3) * STAGE_BYTES;
        uint32_t Ah_b = db, Al_b = db + 8192, Bh_b = db + 16384, Bl_b = db + 24576;

#pragma unroll
        for (int kq = 0; kq < 2; kq++) {
            uint32_t ah[4][4], al[4][4], bhf[4][2], blf[4][2];
            int aj = kq * 2 + a_jk;

            // A-hi
#pragma unroll
            for (int mt = 0; mt < 4; mt++) {
                uint32_t r = (uint32_t)(a_row + mt * 16);
                uint32_t ad = Ah_b + r * 64 + (((uint32_t)aj ^ a_salt) << 4);
                LDSM4(ah[mt][0], ah[mt][1], ah[mt][2], ah[mt][3], ad);
            }
            // B-hi
            if (!transB) {
                int bj = kq * 2 + b_jk;
#pragma unroll
                for (int ntp = 0; ntp < 2; ntp++) {
                    uint32_t r = (uint32_t)(b_row + ntp * 16);
                    uint32_t ad = Bh_b + r * 64 + (((uint32_t)bj ^ b_salt) << 4);
                    uint32_t r0, r1, r2, r3;
                    LDSM4(r0, r1, r2, r3, ad);
                    bhf[2 * ntp][0] = r0; bhf[2 * ntp][1] = r1;
                    bhf[2 * ntp + 1][0] = r2; bhf[2 * ntp + 1][1] = r3;
                }
            } else {
                uint32_t krow = (uint32_t)(kq * 16 + t_krow_in);
                uint32_t sw = (uint32_t)(t_krow_in & 7);
#pragma unroll
                for (int ntp = 0; ntp < 2; ntp++) {
                    uint32_t j = (uint32_t)(t_jbase + ntp * 2);
                    uint32_t ad = Bh_b + krow * 256 + ((j ^ sw) << 4);
                    uint32_t r0, r1, r2, r3;
                    LDSM4T(r0, r1, r2, r3, ad);
                    bhf[2 * ntp][0] = r0; bhf[2 * ntp][1] = r1;
                    bhf[2 * ntp + 1][0] = r2; bhf[2 * ntp + 1][1] = r3;
                }
            }
#pragma unroll
            for (int mt = 0; mt < 4; mt++)
#pragma unroll
                for (int nt = 0; nt < 4; nt++)
                    MMA16816(acc[mt][nt], ah[mt], bhf[nt]);

            // B-lo, term2
            if (!transB) {
                int bj = kq * 2 + b_jk;
#pragma unroll
                for (int ntp = 0; ntp < 2; ntp++) {
                    uint32_t r = (uint32_t)(b_row + ntp * 16);
                    uint32_t ad = Bl_b + r * 64 + (((uint32_t)bj ^ b_salt) << 4);
                    uint32_t r0, r1, r2, r3;
                    LDSM4(r0, r1, r2, r3, ad);
                    blf[2 * ntp][0] = r0; blf[2 * ntp][1] = r1;
                    blf[2 * ntp + 1][0] = r2; blf[2 * ntp + 1][1] = r3;
                }
            } else {
                uint32_t krow = (uint32_t)(kq * 16 + t_krow_in);
                uint32_t sw = (uint32_t)(t_krow_in & 7);
#pragma unroll
                for (int ntp = 0; ntp < 2; ntp++) {
                    uint32_t j = (uint32_t)(t_jbase + ntp * 2);
                    uint32_t ad = Bl_b + krow * 256 + ((j ^ sw) << 4);
                    uint32_t r0, r1, r2, r3;
                    LDSM4T(r0, r1, r2, r3, ad);
                    blf[2 * ntp][0] = r0; blf[2 * ntp][1] = r1;
                    blf[2 * ntp + 1][0] = r2; blf[2 * ntp + 1][1] = r3;
                }
            }
#pragma unroll
            for (int mt = 0; mt < 4; mt++)
#pragma unroll
                for (int nt = 0; nt < 4; nt++)
                    MMA16816(acc[mt][nt], ah[mt], blf[nt]);

            // A-lo, term3
#pragma unroll
            for (int mt = 0; mt < 4; mt++) {
                uint32_t r = (uint32_t)(a_row + mt * 16);
                uint32_t ad = Al_b + r * 64 + (((uint32_t)aj ^ a_salt) << 4);
                LDSM4(al[mt][0], al[mt][1], al[mt][2], al[mt][3], ad);
            }
#pragma unroll
            for (int mt = 0; mt < 4; mt++)
#pragma unroll
                for (int nt = 0; nt < 4; nt++)
                    MMA16816(acc[mt][nt], al[mt], bhf[nt]);
        }
    }

    // ---- epilogue ----
    if (mode == 0) {
        int gm = m0 + warp_m * 64 + (lane >> 2);
#pragma unroll
        for (int mt = 0; mt < 4; mt++)
#pragma unroll
            for (int nt = 0; nt < 4; nt++) {
                int col = n0 + warp_n * 32 + nt * 8 + (lane & 3) * 2;
                int row = gm + mt * 16;
                float* d0 = dst + ((size_t)bh * PP + row) * PP + col;
                *(float2*)d0 = make_float2(acc[mt][nt][0], acc[mt][nt][1]);
                *(float2*)(d0 + 8 * PP) = make_float2(acc[mt][nt][2], acc[mt][nt][3]);
            }
    } else if (mode == 1) {
        int gm = m0 + warp_m * 64 + (lane >> 2);
        int b = bh >> 1, h = bh & 1;
#pragma unroll
        for (int mt = 0; mt < 4; mt++)
#pragma unroll
            for (int nt = 0; nt < 4; nt++) {
                int e = n0 + warp_n * 32 + nt * 8 + (lane & 3) * 2;
                int d = e >> 5, t = e & 31;
                int p = gm + mt * 16;
                float* d0 = dst + (((size_t)b * CC + h * DD + d) * PP + p) * TT + t;
                *(float2*)d0 = make_float2(acc[mt][nt][0], acc[mt][nt][1]);
                *(float2*)(d0 + 8 * TT) = make_float2(acc[mt][nt][2], acc[mt][nt][3]);
            }
    } else {
        // mode 2: QKV epilogue. dst = bias. kind determined by M tile.
        const float* bias = dst;
        int kind = blockIdx.y;                 // 0=q 1=k 2=v
        __nv_bfloat16* dh = (kind == 0) ? g_q_hi : (kind == 1) ? g_k_hi : g_v_hi;
        __nv_bfloat16* dl = (kind == 0) ? g_q_lo : (kind == 1) ? g_k_lo : g_v_lo;
        float mul = (kind == 0) ? 0.125f : 1.0f;
#pragma unroll
        for (int mt = 0; mt < 4; mt++)
#pragma unroll
            for (int nt = 0; nt < 4; nt++) {
                int n = n0 + warp_n * 32 + nt * 8 + (lane & 3) * 2;
                int b = n >> 14;               // / (P*T)
                int p = (n >> 5) & (PP - 1);
                int t = n & (TT - 1);
#pragma unroll
                for (int half = 0; half < 2; half++) {
                    int o = m0 + warp_m * 64 + mt * 16 + (lane >> 2) + half * 8;
                    float bv = __ldg(&bias[o]);
                    int oc = o & (CC - 1);
                    int h = oc >> 6, d = oc & (DD - 1);
                    float v0 = (acc[mt][nt][2 * half + 0] + bv) * mul;
                    float v1 = (acc[mt][nt][2 * half + 1] + bv) * mul;
                    __nv_bfloat16 h2[2], l2[2];
                    split_bf16(v0, h2[0], l2[0]);
                    split_bf16(v1, h2[1], l2[1]);
                    size_t off = (((size_t)b * HH + h) * PP + p) * EE + d * TT + t;
                    *(uint32_t*)(dh + off) = *(const uint32_t*)h2;
                    *(uint32_t*)(dl + off) = *(const uint32_t*)l2;
                }
            }
    }
}

// ---------------------------------------------------------------------------
// K3: row softmax over g_dots; emits attn as bf16 hi/lo splits.
// ---------------------------------------------------------------------------
__global__ void __launch_bounds__(128) softmax_kernel() {
    size_t row = blockIdx.x;
    const float* r = g_dots + row * PP;
    int tid = threadIdx.x;
    float4 v = ((const float4*)r)[tid];

    float m = fmaxf(fmaxf(v.x, v.y), fmaxf(v.z, v.w));
#pragma unroll
    for (int o = 16; o; o >>= 1) m = fmaxf(m, __shfl_xor_sync(0xffffffffu, m, o));
    __shared__ float red[4];
    int wid = tid >> 5;
    if ((tid & 31) == 0) red[wid] = m;
    __syncthreads();
    m = fmaxf(fmaxf(red[0], red[1]), fmaxf(red[2], red[3]));

    v.x = expf(v.x - m); v.y = expf(v.y - m);
    v.z = expf(v.z - m); v.w = expf(v.w - m);
    float s = v.x + v.y + v.z + v.w;
#pragma unroll
    for (int o = 16; o; o >>= 1) s += __shfl_xor_sync(0xffffffffu, s, o);
    __syncthreads();
    if ((tid & 31) == 0) red[wid] = s;
    __syncthreads();
    float inv = 1.0f / (red[0] + red[1] + red[2] + red[3]);
    v.x *= inv; v.y *= inv; v.z *= inv; v.w *= inv;

    __nv_bfloat16 hi[4], lo[4];
    split_bf16(v.x, hi[0], lo[0]); split_bf16(v.y, hi[1], lo[1]);
    split_bf16(v.z, hi[2], lo[2]); split_bf16(v.w, hi[3], lo[3]);
    *(uint2*)(g_attn_hi + row * PP + tid * 4) = *(const uint2*)hi;
    *(uint2*)(g_attn_lo + row * PP + tid * 4) = *(const uint2*)lo;
}

// ---------------------------------------------------------------------------
extern "C" void kernel_launch(void* const* d_in, const int* in_sizes, int n_in,
                              void* d_out, int out_size) {
    const float* x = (const float*)d_in[0];
    const float* W = (const float*)d_in[1];
    const float* b = (const float*)d_in[2];
    float* out = (float*)d_out;

    cudaFuncSetAttribute(mma_nt_kernel, cudaFuncAttributeMaxDynamicSharedMemorySize, MMA_SMEM_REQ);

    wsplit_kernel<<<(O3 * CC + 255) / 256, 256>>>(W);
    xsplit_kernel<<<dim3(PP, BB), 256>>>(x);

    // QKV: D[384, 262144] = W @ xT^T, K=128, NT, mode 2
    {
        __nv_bfloat16 *wh, *wl, *xh, *xl;
        cudaGetSymbolAddress((void**)&wh, g_w_hi);
        cudaGetSymbolAddress((void**)&wl, g_w_lo);
        cudaGetSymbolAddress((void**)&xh, g_xt_hi);
        cudaGetSymbolAddress((void**)&xl, g_xt_lo);
        dim3 g((unsigned)(NN / 128), O3 / 128, 1);
        mma_nt_kernel<<<g, 256, MMA_SMEM_REQ>>>(wh, wl, xh, xl, CC, CC, 0,
                                                0, 0, 2, (float*)b);
    }

    // dots = Qs @ K^T : M=512, N=512, K=2048, NT, mode 0
    {
        float* dots = nullptr;
        cudaGetSymbolAddress((void**)&dots, g_dots);
        __nv_bfloat16 *qh, *ql, *kh, *kl;
        cudaGetSymbolAddress((void**)&qh, g_q_hi);
        cudaGetSymbolAddress((void**)&ql, g_q_lo);
        cudaGetSymbolAddress((void**)&kh, g_k_hi);
        cudaGetSymbolAddress((void**)&kl, g_k_lo);
        dim3 g(PP / 128, PP / 128, BB * HH);
        mma_nt_kernel<<<g, 256, MMA_SMEM_REQ>>>(qh, ql, kh, kl, EE, EE, 0,
                                                (size_t)PP * EE, (size_t)PP * EE, 0, dots);
    }

    softmax_kernel<<<BB * HH * PP, 128>>>();

    // out = attn @ V : M=512, N=2048(E), K=512, NN (trans-B), mode 1
    {
        __nv_bfloat16 *ah, *al, *vh, *vl;
        cudaGetSymbolAddress((void**)&ah, g_attn_hi);
        cudaGetSymbolAddress((void**)&al, g_attn_lo);
        cudaGetSymbolAddress((void**)&vh, g_v_hi);
        cudaGetSymbolAddress((void**)&vl, g_v_lo);
        dim3 g(EE / 128, PP / 128, BB * HH);
        mma_nt_kernel<<<g, 256, MMA_SMEM_REQ>>>(ah, al, vh, vl, PP, EE, 1,
                                                (size_t)PP * PP, (size_t)PP * EE, 1, out);
    }
}